// round 12
// baseline (speedup 1.0000x reference)
#include <cuda_runtime.h>
#include <cuda_fp16.h>
#include <cstdint>

// ============================================================================
// DenseAttention via Gram reassociation — PERSISTENT MEGA-KERNEL (R12).
//   G = Xt Xt^T (sym, 3/4 tiles) ; T = Ws@G ; Pq = T@Ct^T ; P = 2^-10 sum_q Pq
//   out = 2^-10 * Xnt @ P
// Single-pass fp16, fp32 accumulate (rel_err 5.25e-4, unchanged from R11).
// One launch, 144 CTAs (1/SM, all co-resident), 5 grid barriers.
// Cross-stage cp.async prefetch hides s23/s4 prologues under reduce phases.
// ============================================================================

#define HH 65536
#define NCTA 144

__device__ __align__(256) __half g_Xt[8 * 256 * 2048];      // [bq][f][t]
__device__ __align__(256) __half g_Xnt[2 * 2048 * 1024];    // [b][t][e]
__device__ __align__(256) __half g_Wc[16 * HH];             // [aq][e][f] *1024
__device__ __align__(256) __half g_Ct[16 * HH];             // [aq][g'][g] *1024
__device__ __align__(256) float  g_Gpart[6 * 8 * 3 * 16384];
__device__ __align__(256) __half g_G[8 * HH];               // [bq][f][g]
__device__ __align__(256) float  g_Pq[32 * HH];             // [baq][e][g']
__device__ __align__(256) __half g_Pt[8 * HH];              // [ba][g'][e]

__device__ int g_count = 0;
__device__ int g_sense = 0;

// ---------------- PTX helpers ------------------------------------------------
__device__ __forceinline__ uint32_t smem_u32(const void* p) {
    uint32_t a;
    asm("{ .reg .u64 t; cvta.to.shared.u64 t, %1; cvt.u32.u64 %0, t; }" : "=r"(a) : "l"(p));
    return a;
}
__device__ __forceinline__ void cpa16(uint32_t s, const void* g) {
    asm volatile("cp.async.cg.shared.global [%0], [%1], 16;" :: "r"(s), "l"(g));
}
#define CP_COMMIT() asm volatile("cp.async.commit_group;" ::: "memory")
#define CP_WAIT(n)  asm volatile("cp.async.wait_group %0;" :: "n"(n) : "memory")

#define LDSM_X4(r, addr) \
    asm volatile("ldmatrix.sync.aligned.m8n8.x4.shared.b16 {%0,%1,%2,%3}, [%4];" \
        : "=r"((r)[0]), "=r"((r)[1]), "=r"((r)[2]), "=r"((r)[3]) : "r"(addr))

#define MMA_F16(d, a, b0, b1) \
    asm volatile("mma.sync.aligned.m16n8k16.row.col.f32.f16.f16.f32 " \
        "{%0,%1,%2,%3}, {%4,%5,%6,%7}, {%8,%9}, {%0,%1,%2,%3};" \
        : "+f"((d)[0]), "+f"((d)[1]), "+f"((d)[2]), "+f"((d)[3]) \
        : "r"((a)[0]), "r"((a)[1]), "r"((a)[2]), "r"((a)[3]), "r"(b0), "r"(b1))

__device__ __forceinline__ uint2 pack4H(float4 v) {
    union { __half b[4]; uint2 u; } Hq;
    Hq.b[0] = __float2half_rn(v.x); Hq.b[1] = __float2half_rn(v.y);
    Hq.b[2] = __float2half_rn(v.z); Hq.b[3] = __float2half_rn(v.w);
    return Hq.u;
}

// ---------------- grid barrier (all 144 CTAs co-resident) --------------------
__device__ __forceinline__ void gsync(int& sense) {
    __syncthreads();
    if (threadIdx.x == 0) {
        sense ^= 1;
        __threadfence();
        if (atomicAdd(&g_count, 1) == NCTA - 1) {
            g_count = 0;
            asm volatile("st.global.release.gpu.s32 [%0], %1;"
                         :: "l"(&g_sense), "r"(sense) : "memory");
        } else {
            int s;
            do {
                __nanosleep(64);
                asm volatile("ld.global.acquire.gpu.s32 %0, [%1];"
                             : "=r"(s) : "l"(&g_sense) : "memory");
            } while (s != sense);
        }
    }
    __syncthreads();
}

// ---------------- smem layout constants --------------------------------------
#define ROWB   272
// s1 (gemm128): buf c at c*69632; A at +0, B at +34816. total 139264.
#define S1_B    34816
#define S1_BUF  69632
// s23: buf c at c*87040; A at +0, B at +17408. T at 174080 (pitch 528).
#define BUF23   87040
#define B23_OFF 17408
#define T23_OFF 174080
#define ROWB2   528
// s4: buf c at c*104448; A at +0, B at +34816. total 208896.
#define S4_B    34816
#define S4_BUF  104448
#define SMEM_MEGA 208896
// reduce scratch (disjoint from concurrent prefetch targets):
#define RG_SCR  174080   // during reduceG: W prefetch uses [0,17408)+[87040,104448)
#define RP_SCR  34816    // during reduceP: s4 A prefetch uses [0,34816)

// ============================================================================
__global__ void __launch_bounds__(256, 1)
k_mega(const float* __restrict__ hid, const float* __restrict__ qr,
       const float* __restrict__ cb, float* __restrict__ out)
{
    extern __shared__ char smem[];
    const uint32_t sb  = smem_u32(smem);
    const int cta  = blockIdx.x;
    const int tid  = threadIdx.x;
    const int lane = tid & 31;
    const int wid  = tid >> 5;

    int sense = 0;
    if (tid == 0) sense = *(volatile int*)&g_sense;  // stable: no writer until bar1

    // ======================= stage 1: conversions ===========================
    {
        float (*ts)[33] = (float(*)[33])smem;
        for (int blk = cta; blk < 6144; blk += NCTA) {
            if (blk < 4096) {
                int fb = blk & 7, tb = (blk >> 3) & 63, bq = blk >> 9;
                int b = bq >> 2, q = bq & 3;
                int t0 = tb * 32, f0 = fb * 32;
                int tx = tid & 31, ty = tid >> 5;
#pragma unroll
                for (int r = 0; r < 4; r++) {
                    int tt = t0 + ty + r * 8;
                    float v = hid[(size_t)b * 2097152 + (size_t)tt * 1024 + q * 256 + f0 + tx];
                    ts[ty + r * 8][tx] = v;
                    g_Xnt[(size_t)b * 2097152 + (size_t)tt * 1024 + q * 256 + f0 + tx] =
                        __float2half_rn(v);
                }
                __syncthreads();
#pragma unroll
                for (int r = 0; r < 4; r++) {
                    int f = f0 + ty + r * 8;
                    g_Xt[(size_t)bq * 524288 + (size_t)f * 2048 + t0 + tx] =
                        __float2half_rn(ts[tx][ty + r * 8]);
                }
                __syncthreads();
            } else if (blk < 5120) {
                int o4 = (blk - 4096) * 256 + tid;
                int aq = o4 >> 14;
                int rem = (o4 << 2) & 65535;
                int e = rem >> 8, f = rem & 255;
                int a = aq >> 2, q = aq & 3;
                float4 v = *(const float4*)(qr + (size_t)a * 262144 + (size_t)e * 1024 + q * 256 + f);
                v.x *= 1024.f; v.y *= 1024.f; v.z *= 1024.f; v.w *= 1024.f;
                ((uint2*)g_Wc)[o4] = pack4H(v);
            } else {
                int i = blk - 5120;
                int gpb = i & 7, gb = (i >> 3) & 7, aq = i >> 6;
                int a = aq >> 2, q = aq & 3;
                int g0 = gb * 32, gp0 = gpb * 32;
                int tx = tid & 31, ty = tid >> 5;
#pragma unroll
                for (int r = 0; r < 4; r++) {
                    int g = g0 + ty + r * 8;
                    ts[ty + r * 8][tx] =
                        cb[(size_t)a * 262144 + (size_t)(q * 256 + g) * 256 + gp0 + tx] * 1024.f;
                }
                __syncthreads();
#pragma unroll
                for (int r = 0; r < 4; r++) {
                    int gp = gp0 + ty + r * 8;
                    g_Ct[(size_t)aq * 65536 + (size_t)gp * 256 + g0 + tx] =
                        __float2half_rn(ts[tx][ty + r * 8]);
                }
                __syncthreads();
            }
        }
    }
    gsync(sense);

    // ======================= stage 2: s1 Gram (144 units) ====================
    {
        const int t  = cta % 3;
        const int ch = (cta / 3) % 6;
        const int bq = cta / 18;
        const int mt = (t == 2) ? 1 : 0;
        const int nt = (t == 0) ? 0 : 1;
        const int k0g = (ch < 4) ? ch * 384 : 1536 + (ch - 4) * 256;
        const int K   = (ch < 4) ? 384 : 256;

        size_t xo = (size_t)bq * 524288;
        const __half* A = g_Xt + xo + (size_t)mt * 128 * 2048 + k0g;
        const __half* B = g_Xt + xo + (size_t)nt * 128 * 2048 + k0g;
        float* Cf = g_Gpart + (size_t)((ch * 8 + bq) * 3 + t) * 16384;

        const int m0 = (wid >> 1) * 32;
        const int n0 = (wid & 1) * 64;
        const uint32_t aoff = (uint32_t)(m0 + (lane & 15)) * ROWB + ((lane >> 4) << 4);
        const uint32_t boff = (uint32_t)(n0 + ((lane >> 4) << 3) + (lane & 7)) * ROWB
                            + ((lane & 8) ? 16u : 0u);

        float acc[2][8][4];
#pragma unroll
        for (int i = 0; i < 2; i++)
#pragma unroll
            for (int j = 0; j < 8; j++)
#pragma unroll
                for (int r = 0; r < 4; r++) acc[i][j][r] = 0.0f;

        auto load_chunk = [&](int c) {
            const uint32_t bo = sb + (uint32_t)(c & 1) * S1_BUF;
            const int k0 = c << 7;
#pragma unroll
            for (int i = 0; i < 8; i++) {
                int v = i * 256 + tid;
                int r = v >> 4, j = v & 15;
                uint32_t so = (uint32_t)r * ROWB + (uint32_t)j * 16;
                cpa16(bo + so, A + (size_t)r * 2048 + k0 + j * 8);
                cpa16(bo + S1_B + so, B + (size_t)r * 2048 + k0 + j * 8);
            }
        };

        const int NC = K >> 7;
        load_chunk(0);
        CP_COMMIT();
#pragma unroll 1
        for (int c = 0; c < NC; c++) {
            if (c < NC - 1) { load_chunk(c + 1); CP_COMMIT(); CP_WAIT(1); }
            else            { CP_WAIT(0); }
            __syncthreads();
            const uint32_t bo = sb + (uint32_t)(c & 1) * S1_BUF;
            const uint32_t aP = bo + aoff;
            const uint32_t bP = bo + S1_B + boff;
#pragma unroll
            for (int ks = 0; ks < 8; ks++) {
                const uint32_t ko = (uint32_t)ks * 32;
                uint32_t a0[4], a1[4];
                LDSM_X4(a0, aP + ko);
                LDSM_X4(a1, aP + 16 * ROWB + ko);
                uint32_t br[4][4];
#pragma unroll
                for (int p = 0; p < 4; p++)
                    LDSM_X4(br[p], bP + (uint32_t)p * 16 * ROWB + ko);
#pragma unroll
                for (int j = 0; j < 8; j++)
                    MMA_F16(acc[0][j], a0, br[j >> 1][(j & 1) * 2], br[j >> 1][(j & 1) * 2 + 1]);
#pragma unroll
                for (int j = 0; j < 8; j++)
                    MMA_F16(acc[1][j], a1, br[j >> 1][(j & 1) * 2], br[j >> 1][(j & 1) * 2 + 1]);
            }
            __syncthreads();
        }
        const int rr = lane >> 2;
        const int cc = (lane & 3) * 2;
#pragma unroll
        for (int i = 0; i < 2; i++)
#pragma unroll
            for (int j = 0; j < 8; j++) {
                const int row = m0 + i * 16 + rr;
                const int col = n0 + j * 8 + cc;
                float* p = Cf + (size_t)row * 128 + col;
                *(float2*)p = make_float2(acc[i][j][0], acc[i][j][1]);
                *(float2*)(p + 8 * 128) = make_float2(acc[i][j][2], acc[i][j][3]);
            }
    }

    // ---- prefetch s23 W tiles (hidden under reduceG) ------------------------
    if (cta < 128) {
        const int et = cta & 3, baq = cta >> 2;
        const int a = (baq >> 2) & 3, q = baq & 3;
        const __half* Aw = g_Wc + (size_t)(a * 4 + q) * 65536 + (size_t)et * 64 * 256;
#pragma unroll
        for (int c = 0; c < 2; c++) {
            const uint32_t bo = sb + (uint32_t)c * BUF23;
            const int k0 = c << 7;
#pragma unroll
            for (int i = 0; i < 4; i++) {
                int v = i * 256 + tid;
                int r = v >> 4, j = v & 15;
                cpa16(bo + (uint32_t)r * ROWB + (uint32_t)j * 16,
                      Aw + (size_t)r * 256 + k0 + j * 8);
            }
        }
        CP_COMMIT();   // one group: both W chunks
    }
    gsync(sense);

    // ======================= stage 3: reduceG (384 units) ====================
    {
        float (*s)[33] = (float(*)[33])(smem + RG_SCR);
        const int tx = tid & 31, ty = tid >> 5;
        for (int u = cta; u < 384; u += NCTA) {
            const int sub = u % 16, t = (u / 16) % 3, bq = u / 48;
            const int r0 = (sub >> 2) * 32, c0 = (sub & 3) * 32;
            const int br = (t == 2) ? 128 : 0;
            const int bc = (t == 0) ? 0 : 128;
            float v[4];
#pragma unroll
            for (int k = 0; k < 4; k++) {
                const int r = r0 + ty + k * 8;
                float a = 0.f;
#pragma unroll
                for (int ch = 0; ch < 6; ch++)
                    a += g_Gpart[(size_t)((ch * 8 + bq) * 3 + t) * 16384 + r * 128 + c0 + tx];
                v[k] = a;
                s[ty + k * 8][tx] = a;
            }
#pragma unroll
            for (int k = 0; k < 4; k++)
                g_G[(size_t)bq * 65536 + (size_t)(br + r0 + ty + k * 8) * 256 + bc + c0 + tx] =
                    __float2half_rn(v[k]);
            if (t == 1) {
                __syncthreads();
#pragma unroll
                for (int k = 0; k < 4; k++)
                    g_G[(size_t)bq * 65536 + (size_t)(128 + c0 + ty + k * 8) * 256 + r0 + tx] =
                        __float2half_rn(s[tx][ty + k * 8]);
            }
            __syncthreads();
        }
    }
    gsync(sense);

    // ======================= stage 4: s23 fused (128 units) ==================
    if (cta < 128) {
        const int et = cta & 3, baq = cta >> 2;
        const int b = baq >> 4, a = (baq >> 2) & 3, q = baq & 3;
        const int aq = a * 4 + q, bq = b * 4 + q;
        const __half* Bg = g_G  + (size_t)bq * 65536;
        const __half* Bc = g_Ct + (size_t)aq * 65536;

        const int m0 = (wid & 1) * 32;
        const int n0 = (wid >> 1) * 64;
        const uint32_t aoff  = (uint32_t)(m0 + (lane & 15)) * ROWB + ((lane >> 4) << 4);
        const uint32_t aoff2 = (uint32_t)(m0 + (lane & 15)) * ROWB2 + ((lane >> 4) << 4);
        const uint32_t boff  = (uint32_t)(n0 + ((lane >> 4) << 3) + (lane & 7)) * ROWB
                             + ((lane & 8) ? 16u : 0u);
        const int rr = lane >> 2;
        const int cc = (lane & 3) * 2;

        float acc[2][8][4];
        auto load_B = [&](int c, const __half* B) {
            const uint32_t bo = sb + (uint32_t)(c & 1) * BUF23 + B23_OFF;
            const int k0 = c << 7;
#pragma unroll
            for (int i = 0; i < 16; i++) {
                int v = i * 256 + tid;
                int r = v >> 4, j = v & 15;
                cpa16(bo + (uint32_t)r * ROWB + (uint32_t)j * 16,
                      B + (size_t)r * 256 + k0 + j * 8);
            }
        };
        auto zero_acc = [&]() {
#pragma unroll
            for (int i = 0; i < 2; i++)
#pragma unroll
                for (int j = 0; j < 8; j++)
#pragma unroll
                    for (int r = 0; r < 4; r++) acc[i][j][r] = 0.0f;
        };
        auto mma_chunk = [&](uint32_t aP, uint32_t arowb, uint32_t bP) {
#pragma unroll
            for (int ks = 0; ks < 8; ks++) {
                const uint32_t ko = (uint32_t)ks * 32;
                uint32_t a0[4], a1[4];
                LDSM_X4(a0, aP + ko);
                LDSM_X4(a1, aP + 16 * arowb + ko);
                uint32_t br[4][4];
#pragma unroll
                for (int p = 0; p < 4; p++)
                    LDSM_X4(br[p], bP + (uint32_t)p * 16 * ROWB + ko);
#pragma unroll
                for (int j = 0; j < 8; j++)
                    MMA_F16(acc[0][j], a0, br[j >> 1][(j & 1) * 2], br[j >> 1][(j & 1) * 2 + 1]);
#pragma unroll
                for (int j = 0; j < 8; j++)
                    MMA_F16(acc[1][j], a1, br[j >> 1][(j & 1) * 2], br[j >> 1][(j & 1) * 2 + 1]);
            }
        };

        // phase 1: T = Ws @ G (W already prefetched into buf0.A / buf1.A)
        zero_acc();
        load_B(0, Bg); CP_COMMIT();                    // G c0
        load_B(1, Bg); CP_COMMIT();                    // G c1
        CP_WAIT(1);                                    // W-group + G c0 done
        __syncthreads();
        mma_chunk(sb + aoff, ROWB, sb + B23_OFF + boff);
        __syncthreads();
        load_B(0, Bc); CP_COMMIT();                    // Ct c0 -> buf0.B
        CP_WAIT(1);                                    // G c1 done
        __syncthreads();
        mma_chunk(sb + BUF23 + aoff, ROWB, sb + BUF23 + B23_OFF + boff);
        __syncthreads();
        load_B(1, Bc); CP_COMMIT();                    // Ct c1 -> buf1.B

        // T epilogue -> SMEM fp16 (pitch 528B)
        {
            char* Tb = smem + T23_OFF;
#pragma unroll
            for (int i = 0; i < 2; i++)
#pragma unroll
                for (int j = 0; j < 8; j++) {
                    const int row = m0 + i * 16 + rr;
                    const int col = n0 + j * 8 + cc;
                    *(__half2*)(Tb + (size_t)row * ROWB2 + col * 2) =
                        __halves2half2(__float2half_rn(acc[i][j][0]), __float2half_rn(acc[i][j][1]));
                    *(__half2*)(Tb + (size_t)(row + 8) * ROWB2 + col * 2) =
                        __halves2half2(__float2half_rn(acc[i][j][2]), __float2half_rn(acc[i][j][3]));
                }
        }

        // phase 2: Pq = T @ Ct^T
        zero_acc();
        CP_WAIT(1);                                    // Ct c0 done
        __syncthreads();
        mma_chunk(sb + T23_OFF + aoff2, ROWB2, sb + B23_OFF + boff);
        CP_WAIT(0);
        __syncthreads();
        mma_chunk(sb + T23_OFF + aoff2 + 256, ROWB2, sb + BUF23 + B23_OFF + boff);

        float* Cf = g_Pq + (size_t)baq * 65536 + (size_t)et * 64 * 256;
#pragma unroll
        for (int i = 0; i < 2; i++)
#pragma unroll
            for (int j = 0; j < 8; j++) {
                const int row = m0 + i * 16 + rr;
                const int col = n0 + j * 8 + cc;
                float* p = Cf + (size_t)row * 256 + col;
                *(float2*)p = make_float2(acc[i][j][0], acc[i][j][1]);
                *(float2*)(p + 8 * 256) = make_float2(acc[i][j][2], acc[i][j][3]);
            }
    }

    // ---- prefetch s4 A chunk0 (hidden under reduceP) ------------------------
    if (cta < 128) {
        const int mt = cta & 15, ba = cta >> 4;
        const int b = ba >> 2, a = ba & 3;
        const __half* A = g_Xnt + (size_t)b * 2097152 + (size_t)mt * 128 * 1024 + a * 256;
#pragma unroll
        for (int i = 0; i < 8; i++) {
            int v = i * 256 + tid;
            int r = v >> 4, j = v & 15;
            cpa16(sb + (uint32_t)r * ROWB + (uint32_t)j * 16,
                  A + (size_t)r * 1024 + j * 8);
        }
        CP_COMMIT();
    }
    gsync(sense);

    // ======================= stage 5: reduceP (512 units) ====================
    {
        float (*t)[33] = (float(*)[33])(smem + RP_SCR);
        const int tx = tid & 31, ty = tid >> 5;
        const float ds = 1.0f / 1024.0f;
        for (int u = cta; u < 512; u += NCTA) {
            const int gpb = u % 8, eb = (u / 8) % 8, ba = u / 64;
            const int b = ba >> 2, a = ba & 3;
            const int e0 = eb * 32, gp0 = gpb * 32;
#pragma unroll
            for (int r = 0; r < 4; r++) {
                const int e = e0 + ty + r * 8;
                float s = 0.f;
#pragma unroll
                for (int q = 0; q < 4; q++)
                    s += g_Pq[(size_t)(b * 16 + a * 4 + q) * 65536 + (size_t)e * 256 + gp0 + tx];
                t[ty + r * 8][tx] = s;
            }
            __syncthreads();
#pragma unroll
            for (int r = 0; r < 4; r++) {
                const int gp = gp0 + ty + r * 8;
                g_Pt[(size_t)ba * 65536 + (size_t)gp * 256 + e0 + tx] =
                    __float2half_rn(t[tx][ty + r * 8] * ds);
            }
            __syncthreads();
        }
    }
    gsync(sense);

    // ======================= stage 6: s4 (128 units) =========================
    if (cta < 128) {
        const int mt = cta & 15, ba = cta >> 4;
        const int b = ba >> 2, a = ba & 3;
        const __half* A = g_Xnt + (size_t)b * 2097152 + (size_t)mt * 128 * 1024 + a * 256;
        const __half* B = g_Pt + (size_t)ba * 65536;
        float* Cf = out + (size_t)b * 2097152 + (size_t)mt * 128 * 1024 + a * 256;

        const int mw = (wid >> 2) * 64;
        const int nw = (wid & 3) * 64;
        const uint32_t aoff = (uint32_t)(mw + (lane & 15)) * ROWB + ((lane >> 4) << 4);
        const uint32_t boff = (uint32_t)(nw + ((lane >> 4) << 3) + (lane & 7)) * ROWB
                            + ((lane & 8) ? 16u : 0u);

        float acc[4][8][4];
#pragma unroll
        for (int i = 0; i < 4; i++)
#pragma unroll
            for (int j = 0; j < 8; j++)
#pragma unroll
                for (int r = 0; r < 4; r++) acc[i][j][r] = 0.0f;

        // B c0
        {
            const int k0 = 0;
#pragma unroll
            for (int i = 0; i < 16; i++) {
                int v = i * 256 + tid;
                int r = v >> 4, j = v & 15;
                cpa16(sb + S4_B + (uint32_t)r * ROWB + (uint32_t)j * 16,
                      B + (size_t)r * 256 + k0 + j * 8);
            }
            CP_COMMIT();
        }
        // A+B c1
        {
            const int k0 = 128;
            const uint32_t bo = sb + S4_BUF;
#pragma unroll
            for (int i = 0; i < 8; i++) {
                int v = i * 256 + tid;
                int r = v >> 4, j = v & 15;
                cpa16(bo + (uint32_t)r * ROWB + (uint32_t)j * 16,
                      A + (size_t)r * 1024 + k0 + j * 8);
            }
#pragma unroll
            for (int i = 0; i < 16; i++) {
                int v = i * 256 + tid;
                int r = v >> 4, j = v & 15;
                cpa16(bo + S4_B + (uint32_t)r * ROWB + (uint32_t)j * 16,
                      B + (size_t)r * 256 + k0 + j * 8);
            }
            CP_COMMIT();
        }

#pragma unroll 1
        for (int c = 0; c < 2; c++) {
            if (c == 0) CP_WAIT(1);
            else        CP_WAIT(0);
            __syncthreads();
            const uint32_t bo = sb + (uint32_t)c * S4_BUF;
            const uint32_t aP = bo + aoff;
            const uint32_t bP = bo + S4_B + boff;
#pragma unroll
            for (int ks = 0; ks < 8; ks++) {
                const uint32_t ko = (uint32_t)ks * 32;
                uint32_t af[4][4];
#pragma unroll
                for (int i = 0; i < 4; i++)
                    LDSM_X4(af[i], aP + (uint32_t)i * 16 * ROWB + ko);
                uint32_t br[4][4];
#pragma unroll
                for (int p = 0; p < 4; p++)
                    LDSM_X4(br[p], bP + (uint32_t)p * 16 * ROWB + ko);
#pragma unroll
                for (int i = 0; i < 4; i++)
#pragma unroll
                    for (int j = 0; j < 8; j++)
                        MMA_F16(acc[i][j], af[i], br[j >> 1][(j & 1) * 2], br[j >> 1][(j & 1) * 2 + 1]);
            }
            __syncthreads();
        }

        const int rr = lane >> 2;
        const int cc = (lane & 3) * 2;
        const float ds = 1.0f / 1024.0f;
#pragma unroll
        for (int i = 0; i < 4; i++)
#pragma unroll
            for (int j = 0; j < 8; j++) {
                const int row = mw + i * 16 + rr;
                const int col = nw + j * 8 + cc;
                float* p = Cf + (size_t)row * 1024 + col;
                *(float2*)p = make_float2(acc[i][j][0] * ds, acc[i][j][1] * ds);
                *(float2*)(p + (size_t)8 * 1024) =
                    make_float2(acc[i][j][2] * ds, acc[i][j][3] * ds);
            }
    }
}

// ============================================================================
extern "C" void kernel_launch(void* const* d_in, const int* in_sizes, int n_in,
                              void* d_out, int out_size)
{
    const float* hidden    = (const float*)d_in[0];  // [2,2048,1024]
    const float* queries   = (const float*)d_in[1];  // [4,256,1024]
    const float* combiners = (const float*)d_in[2];  // [4,1024,256]
    float* out = (float*)d_out;
    (void)in_sizes; (void)n_in; (void)out_size;

    cudaFuncSetAttribute(k_mega, cudaFuncAttributeMaxDynamicSharedMemorySize, SMEM_MEGA);
    k_mega<<<NCTA, 256, SMEM_MEGA>>>(hidden, queries, combiners, out);
}

// round 13
// speedup vs baseline: 1.5862x; 1.5862x over previous
#include <cuda_runtime.h>
#include <cuda_fp16.h>
#include <cstdint>

// ============================================================================
// DenseAttention via Gram reassociation (R11 math, rel_err 5.2486e-4):
//   G = Xt Xt^T (sym, 3/4 tiles) ; T = Ws@G ; Pq = T@Ct^T ; P = 2^-10 sum_q Pq
//   out = 2^-10 * Xnt @ P
// R13: R11 kernels + PDL (programmatic dependent launch). griddepcontrol.wait /
// launch_dependents telescope the 6-kernel chain: launch gaps overlap producer
// tails, and s23/s4 prefetch their conv-produced operands BEFORE the wait.
// ============================================================================

#define HH 65536

__device__ __align__(256) __half g_Xt[8 * 256 * 2048];      // [bq][f][t]
__device__ __align__(256) __half g_Xnt[2 * 2048 * 1024];    // [b][t][e]
__device__ __align__(256) __half g_Wc[16 * HH];             // [aq][e][f] *1024
__device__ __align__(256) __half g_Ct[16 * HH];             // [aq][g'][g] *1024
__device__ __align__(256) float  g_Gpart[6 * 8 * 3 * 16384];
__device__ __align__(256) __half g_G[8 * HH];               // [bq][f][g]
__device__ __align__(256) float  g_Pq[32 * HH];             // [baq][e][g']
__device__ __align__(256) __half g_Pt[8 * HH];              // [ba][g'][e]

// ---------------- PTX helpers ------------------------------------------------
__device__ __forceinline__ uint32_t smem_u32(const void* p) {
    uint32_t a;
    asm("{ .reg .u64 t; cvta.to.shared.u64 t, %1; cvt.u32.u64 %0, t; }" : "=r"(a) : "l"(p));
    return a;
}
__device__ __forceinline__ void cpa16(uint32_t s, const void* g) {
    asm volatile("cp.async.cg.shared.global [%0], [%1], 16;" :: "r"(s), "l"(g));
}
#define CP_COMMIT() asm volatile("cp.async.commit_group;" ::: "memory")
#define CP_WAIT(n)  asm volatile("cp.async.wait_group %0;" :: "n"(n) : "memory")

#define GDC_WAIT()   asm volatile("griddepcontrol.wait;" ::: "memory")
#define GDC_LAUNCH() asm volatile("griddepcontrol.launch_dependents;")

#define LDSM_X4(r, addr) \
    asm volatile("ldmatrix.sync.aligned.m8n8.x4.shared.b16 {%0,%1,%2,%3}, [%4];" \
        : "=r"((r)[0]), "=r"((r)[1]), "=r"((r)[2]), "=r"((r)[3]) : "r"(addr))

#define MMA_F16(d, a, b0, b1) \
    asm volatile("mma.sync.aligned.m16n8k16.row.col.f32.f16.f16.f32 " \
        "{%0,%1,%2,%3}, {%4,%5,%6,%7}, {%8,%9}, {%0,%1,%2,%3};" \
        : "+f"((d)[0]), "+f"((d)[1]), "+f"((d)[2]), "+f"((d)[3]) \
        : "r"((a)[0]), "r"((a)[1]), "r"((a)[2]), "r"((a)[3]), "r"(b0), "r"(b1))

__device__ __forceinline__ uint2 pack4H(float4 v) {
    union { __half b[4]; uint2 u; } Hq;
    Hq.b[0] = __float2half_rn(v.x); Hq.b[1] = __float2half_rn(v.y);
    Hq.b[2] = __float2half_rn(v.z); Hq.b[3] = __float2half_rn(v.w);
    return Hq.u;
}

// ============================================================================
// Generic 128x128 tile GEMM (s1): 256 threads, 8 warps 4Mx2N (32x64 warp
// tile), BK=128 double-buffered cp.async, fp16 single-pass, fp32 accum.
// ============================================================================
#define ROWB   272
#define S1_B   34816
#define S1_BUF 69632
#define SMEM_G (2 * S1_BUF)

__device__ __forceinline__ void gemm128(
    const __half* __restrict__ A, int lda,
    const __half* __restrict__ B, int ldb,
    int K, float* __restrict__ Cf, int ldc)
{
    extern __shared__ char smem[];
    const uint32_t sb  = smem_u32(smem);
    const int tid  = threadIdx.x;
    const int lane = tid & 31;
    const int wid  = tid >> 5;
    const int m0   = (wid >> 1) * 32;
    const int n0   = (wid & 1) * 64;

    const uint32_t aoff = (uint32_t)(m0 + (lane & 15)) * ROWB + ((lane >> 4) << 4);
    const uint32_t boff = (uint32_t)(n0 + ((lane >> 4) << 3) + (lane & 7)) * ROWB
                        + ((lane & 8) ? 16u : 0u);

    float acc[2][8][4];
#pragma unroll
    for (int i = 0; i < 2; i++)
#pragma unroll
        for (int j = 0; j < 8; j++)
#pragma unroll
            for (int r = 0; r < 4; r++) acc[i][j][r] = 0.0f;

    auto load_chunk = [&](int c) {
        const uint32_t bo = sb + (uint32_t)(c & 1) * S1_BUF;
        const int k0 = c << 7;
#pragma unroll
        for (int i = 0; i < 8; i++) {
            int v = i * 256 + tid;
            int r = v >> 4, j = v & 15;
            uint32_t so = (uint32_t)r * ROWB + (uint32_t)j * 16;
            cpa16(bo + so, A + (size_t)r * lda + k0 + j * 8);
            cpa16(bo + S1_B + so, B + (size_t)r * ldb + k0 + j * 8);
        }
    };

    const int NC = K >> 7;
    load_chunk(0);
    CP_COMMIT();

#pragma unroll 1
    for (int c = 0; c < NC; c++) {
        if (c < NC - 1) { load_chunk(c + 1); CP_COMMIT(); CP_WAIT(1); }
        else            { CP_WAIT(0); }
        __syncthreads();

        const uint32_t bo = sb + (uint32_t)(c & 1) * S1_BUF;
        const uint32_t aP = bo + aoff;
        const uint32_t bP = bo + S1_B + boff;

#pragma unroll
        for (int ks = 0; ks < 8; ks++) {
            const uint32_t ko = (uint32_t)ks * 32;
            uint32_t a0[4], a1[4];
            LDSM_X4(a0, aP + ko);
            LDSM_X4(a1, aP + 16 * ROWB + ko);
            uint32_t br[4][4];
#pragma unroll
            for (int p = 0; p < 4; p++)
                LDSM_X4(br[p], bP + (uint32_t)p * 16 * ROWB + ko);
#pragma unroll
            for (int j = 0; j < 8; j++)
                MMA_F16(acc[0][j], a0, br[j >> 1][(j & 1) * 2], br[j >> 1][(j & 1) * 2 + 1]);
#pragma unroll
            for (int j = 0; j < 8; j++)
                MMA_F16(acc[1][j], a1, br[j >> 1][(j & 1) * 2], br[j >> 1][(j & 1) * 2 + 1]);
        }
        __syncthreads();
    }

    const int rr = lane >> 2;
    const int cc = (lane & 3) * 2;
#pragma unroll
    for (int i = 0; i < 2; i++)
#pragma unroll
        for (int j = 0; j < 8; j++) {
            const int row = m0 + i * 16 + rr;
            const int col = n0 + j * 8 + cc;
            float* p = Cf + (size_t)row * ldc + col;
            *(float2*)p = make_float2(acc[i][j][0], acc[i][j][1]);
            *(float2*)(p + (size_t)8 * ldc) = make_float2(acc[i][j][2], acc[i][j][3]);
        }
}

// ============================================================================
// FUSED s2+s3 kernel: 64x256 tiles, 256 threads (8 warps: 2M x 4N, warp 32x64).
// W tiles prefetched BEFORE griddepcontrol.wait (conv output, transitively
// complete). Then G/Ct flow as in R11.
// ============================================================================
#define BUF23   87040
#define B23_OFF 17408
#define T23_OFF 174080
#define ROWB2   528
#define SMEM_23 207872

__global__ void __launch_bounds__(256)
k_s23()  // grid (et 4, 1, baq 32) = 128 CTAs
{
    extern __shared__ char smem[];
    const uint32_t sb  = smem_u32(smem);
    const int tid  = threadIdx.x;
    const int lane = tid & 31;
    const int wid  = tid >> 5;
    const int m0   = (wid & 1) * 32;
    const int n0   = (wid >> 1) * 64;
    const int et   = blockIdx.x;
    const int baq  = blockIdx.z;
    const int b = baq >> 4, a = (baq >> 2) & 3, q = baq & 3;
    const int aq = a * 4 + q, bq = b * 4 + q;

    const __half* Aw = g_Wc + (size_t)aq * 65536 + (size_t)et * 64 * 256;
    const __half* Bg = g_G  + (size_t)bq * 65536;
    const __half* Bc = g_Ct + (size_t)aq * 65536;

    // ---- pre-wait prefetch: W chunks 0/1 -> buf0.A / buf1.A (one group) ----
#pragma unroll
    for (int c = 0; c < 2; c++) {
        const uint32_t bo = sb + (uint32_t)c * BUF23;
        const int k0 = c << 7;
#pragma unroll
        for (int i = 0; i < 4; i++) {
            int v = i * 256 + tid;
            int r = v >> 4, j = v & 15;
            cpa16(bo + (uint32_t)r * ROWB + (uint32_t)j * 16,
                  Aw + (size_t)r * 256 + k0 + j * 8);
        }
    }
    CP_COMMIT();

    GDC_WAIT();     // reduceG (G producer) complete
    GDC_LAUNCH();   // let reduceP launch under our execution

    const uint32_t aoff  = (uint32_t)(m0 + (lane & 15)) * ROWB + ((lane >> 4) << 4);
    const uint32_t aoff2 = (uint32_t)(m0 + (lane & 15)) * ROWB2 + ((lane >> 4) << 4);
    const uint32_t boff  = (uint32_t)(n0 + ((lane >> 4) << 3) + (lane & 7)) * ROWB
                         + ((lane & 8) ? 16u : 0u);
    const int rr = lane >> 2;
    const int cc = (lane & 3) * 2;

    float acc[2][8][4];

    auto load_B = [&](int c, const __half* B) {
        const uint32_t bo = sb + (uint32_t)(c & 1) * BUF23 + B23_OFF;
        const int k0 = c << 7;
#pragma unroll
        for (int i = 0; i < 16; i++) {
            int v = i * 256 + tid;
            int r = v >> 4, j = v & 15;
            cpa16(bo + (uint32_t)r * ROWB + (uint32_t)j * 16,
                  B + (size_t)r * 256 + k0 + j * 8);
        }
    };
    auto zero_acc = [&]() {
#pragma unroll
        for (int i = 0; i < 2; i++)
#pragma unroll
            for (int j = 0; j < 8; j++)
#pragma unroll
                for (int r = 0; r < 4; r++) acc[i][j][r] = 0.0f;
    };
    auto mma_chunk = [&](uint32_t aP, uint32_t arowb, uint32_t bP) {
#pragma unroll
        for (int ks = 0; ks < 8; ks++) {
            const uint32_t ko = (uint32_t)ks * 32;
            uint32_t a0[4], a1[4];
            LDSM_X4(a0, aP + ko);
            LDSM_X4(a1, aP + 16 * arowb + ko);
            uint32_t br[4][4];
#pragma unroll
            for (int p = 0; p < 4; p++)
                LDSM_X4(br[p], bP + (uint32_t)p * 16 * ROWB + ko);
#pragma unroll
            for (int j = 0; j < 8; j++)
                MMA_F16(acc[0][j], a0, br[j >> 1][(j & 1) * 2], br[j >> 1][(j & 1) * 2 + 1]);
#pragma unroll
            for (int j = 0; j < 8; j++)
                MMA_F16(acc[1][j], a1, br[j >> 1][(j & 1) * 2], br[j >> 1][(j & 1) * 2 + 1]);
        }
    };

    // phase 1: T = Ws @ G (W already in buf0.A / buf1.A)
    zero_acc();
    load_B(0, Bg); CP_COMMIT();                    // {W},{G0}
    load_B(1, Bg); CP_COMMIT();                    // {W},{G0},{G1}
    CP_WAIT(1);                                    // W + G0 done
    __syncthreads();
    mma_chunk(sb + aoff, ROWB, sb + B23_OFF + boff);
    __syncthreads();
    load_B(0, Bc); CP_COMMIT();                    // Ct c0 -> buf0.B
    CP_WAIT(1);                                    // G1 done
    __syncthreads();
    mma_chunk(sb + BUF23 + aoff, ROWB, sb + BUF23 + B23_OFF + boff);
    __syncthreads();
    load_B(1, Bc); CP_COMMIT();                    // Ct c1 -> buf1.B

    // T epilogue -> SMEM fp16 (pitch 528B)
    {
        char* Tb = smem + T23_OFF;
#pragma unroll
        for (int i = 0; i < 2; i++)
#pragma unroll
            for (int j = 0; j < 8; j++) {
                const int row = m0 + i * 16 + rr;
                const int col = n0 + j * 8 + cc;
                *(__half2*)(Tb + (size_t)row * ROWB2 + col * 2) =
                    __halves2half2(__float2half_rn(acc[i][j][0]), __float2half_rn(acc[i][j][1]));
                *(__half2*)(Tb + (size_t)(row + 8) * ROWB2 + col * 2) =
                    __halves2half2(__float2half_rn(acc[i][j][2]), __float2half_rn(acc[i][j][3]));
            }
    }

    // phase 2: Pq = T @ Ct^T
    zero_acc();
    CP_WAIT(1);                                    // Ct c0 done
    __syncthreads();
    mma_chunk(sb + T23_OFF + aoff2, ROWB2, sb + B23_OFF + boff);
    CP_WAIT(0);
    __syncthreads();
    mma_chunk(sb + T23_OFF + aoff2 + 256, ROWB2, sb + BUF23 + B23_OFF + boff);

    float* Cf = g_Pq + (size_t)baq * 65536 + (size_t)et * 64 * 256;
#pragma unroll
    for (int i = 0; i < 2; i++)
#pragma unroll
        for (int j = 0; j < 8; j++) {
            const int row = m0 + i * 16 + rr;
            const int col = n0 + j * 8 + cc;
            float* p = Cf + (size_t)row * 256 + col;
            *(float2*)p = make_float2(acc[i][j][0], acc[i][j][1]);
            *(float2*)(p + 8 * 256) = make_float2(acc[i][j][2], acc[i][j][3]);
        }
}

// ============================================================================
// s4: 128x256 tile, 8 warps 2Mx4N (64x64 warp tile), BK=128, single wave.
// A chunk0 (Xnt, conv output) prefetched BEFORE griddepcontrol.wait.
// ============================================================================
#define S4_B    34816
#define S4_BUF  104448
#define SMEM_S4 208896

__global__ void __launch_bounds__(256)
k_s4(float* __restrict__ out)   // grid (16, 1, 8) = 128 CTAs
{
    extern __shared__ char smem[];
    const uint32_t sb  = smem_u32(smem);
    const int tid  = threadIdx.x;
    const int lane = tid & 31;
    const int wid  = tid >> 5;
    const int mw   = (wid >> 2) * 64;
    const int nw   = (wid & 3) * 64;
    const int mt = blockIdx.x, ba = blockIdx.z;
    const int b = ba >> 2, a = ba & 3;

    const __half* A = g_Xnt + (size_t)b * 2097152 + (size_t)mt * 128 * 1024 + a * 256;
    const __half* B = g_Pt + (size_t)ba * 65536;
    float* Cf = out + (size_t)b * 2097152 + (size_t)mt * 128 * 1024 + a * 256;

    // ---- pre-wait prefetch: A chunk0 -> buf0.A ------------------------------
#pragma unroll
    for (int i = 0; i < 8; i++) {
        int v = i * 256 + tid;
        int r = v >> 4, j = v & 15;
        cpa16(sb + (uint32_t)r * ROWB + (uint32_t)j * 16,
              A + (size_t)r * 1024 + j * 8);
    }
    CP_COMMIT();                                   // {A0}

    GDC_WAIT();                                    // reduceP (Pt producer) done

    const uint32_t aoff = (uint32_t)(mw + (lane & 15)) * ROWB + ((lane >> 4) << 4);
    const uint32_t boff = (uint32_t)(nw + ((lane >> 4) << 3) + (lane & 7)) * ROWB
                        + ((lane & 8) ? 16u : 0u);

    float acc[4][8][4];
#pragma unroll
    for (int i = 0; i < 4; i++)
#pragma unroll
        for (int j = 0; j < 8; j++)
#pragma unroll
            for (int r = 0; r < 4; r++) acc[i][j][r] = 0.0f;

    // B c0
#pragma unroll
    for (int i = 0; i < 16; i++) {
        int v = i * 256 + tid;
        int r = v >> 4, j = v & 15;
        cpa16(sb + S4_B + (uint32_t)r * ROWB + (uint32_t)j * 16,
              B + (size_t)r * 256 + j * 8);
    }
    CP_COMMIT();                                   // {A0},{B0}
    // A+B c1
    {
        const uint32_t bo = sb + S4_BUF;
#pragma unroll
        for (int i = 0; i < 8; i++) {
            int v = i * 256 + tid;
            int r = v >> 4, j = v & 15;
            cpa16(bo + (uint32_t)r * ROWB + (uint32_t)j * 16,
                  A + (size_t)r * 1024 + 128 + j * 8);
        }
#pragma unroll
        for (int i = 0; i < 16; i++) {
            int v = i * 256 + tid;
            int r = v >> 4, j = v & 15;
            cpa16(bo + S4_B + (uint32_t)r * ROWB + (uint32_t)j * 16,
                  B + (size_t)r * 256 + 128 + j * 8);
        }
        CP_COMMIT();                               // {A0},{B0},{A1B1}
    }

#pragma unroll 1
    for (int c = 0; c < 2; c++) {
        if (c == 0) CP_WAIT(1);                    // A0 + B0 done
        else        CP_WAIT(0);
        __syncthreads();
        const uint32_t bo = sb + (uint32_t)c * S4_BUF;
        const uint32_t aP = bo + aoff;
        const uint32_t bP = bo + S4_B + boff;
#pragma unroll
        for (int ks = 0; ks < 8; ks++) {
            const uint32_t ko = (uint32_t)ks * 32;
            uint32_t af[4][4];
#pragma unroll
            for (int i = 0; i < 4; i++)
                LDSM_X4(af[i], aP + (uint32_t)i * 16 * ROWB + ko);
            uint32_t br[4][4];
#pragma unroll
            for (int p = 0; p < 4; p++)
                LDSM_X4(br[p], bP + (uint32_t)p * 16 * ROWB + ko);
#pragma unroll
            for (int i = 0; i < 4; i++)
#pragma unroll
                for (int j = 0; j < 8; j++)
                    MMA_F16(acc[i][j], af[i], br[j >> 1][(j & 1) * 2], br[j >> 1][(j & 1) * 2 + 1]);
        }
        __syncthreads();
    }

    const int rr = lane >> 2;
    const int cc = (lane & 3) * 2;
    const float ds = 1.0f / 1024.0f;
#pragma unroll
    for (int i = 0; i < 4; i++)
#pragma unroll
        for (int j = 0; j < 8; j++) {
            const int row = mw + i * 16 + rr;
            const int col = nw + j * 8 + cc;
            float* p = Cf + (size_t)row * 1024 + col;
            *(float2*)p = make_float2(acc[i][j][0] * ds, acc[i][j][1] * ds);
            *(float2*)(p + (size_t)8 * 1024) =
                make_float2(acc[i][j][2] * ds, acc[i][j][3] * ds);
        }
}

// ============================================================================
// fused conversion kernel: grid 6144 blocks x 256 (first in chain; no wait)
// ============================================================================
__global__ void k_conv(const float* __restrict__ hid,
                       const float* __restrict__ qr,
                       const float* __restrict__ cb)
{
    __shared__ float ts[32][33];
    const int blk = blockIdx.x;
    const int tid = threadIdx.x;

    if (blk < 4096) {
        int i = blk;
        int fb = i & 7, tb = (i >> 3) & 63, bq = i >> 9;
        int b = bq >> 2, q = bq & 3;
        int t0 = tb * 32, f0 = fb * 32;
        int tx = tid & 31, ty = tid >> 5;
#pragma unroll
        for (int r = 0; r < 4; r++) {
            int tt = t0 + ty + r * 8;
            float v = hid[(size_t)b * 2097152 + (size_t)tt * 1024 + q * 256 + f0 + tx];
            ts[ty + r * 8][tx] = v;
            g_Xnt[(size_t)b * 2097152 + (size_t)tt * 1024 + q * 256 + f0 + tx] =
                __float2half_rn(v);
        }
        __syncthreads();
#pragma unroll
        for (int r = 0; r < 4; r++) {
            int f = f0 + ty + r * 8;
            g_Xt[(size_t)bq * 524288 + (size_t)f * 2048 + t0 + tx] =
                __float2half_rn(ts[tx][ty + r * 8]);
        }
    } else if (blk < 5120) {
        int o4 = (blk - 4096) * 256 + tid;
        int aq = o4 >> 14;
        int rem = (o4 << 2) & 65535;
        int e = rem >> 8, f = rem & 255;
        int a = aq >> 2, q = aq & 3;
        float4 v = *(const float4*)(qr + (size_t)a * 262144 + (size_t)e * 1024 + q * 256 + f);
        v.x *= 1024.f; v.y *= 1024.f; v.z *= 1024.f; v.w *= 1024.f;
        ((uint2*)g_Wc)[o4] = pack4H(v);
    } else {
        int i = blk - 5120;
        int gpb = i & 7, gb = (i >> 3) & 7, aq = i >> 6;
        int a = aq >> 2, q = aq & 3;
        int g0 = gb * 32, gp0 = gpb * 32;
        int tx = tid & 31, ty = tid >> 5;
#pragma unroll
        for (int r = 0; r < 4; r++) {
            int g = g0 + ty + r * 8;
            ts[ty + r * 8][tx] =
                cb[(size_t)a * 262144 + (size_t)(q * 256 + g) * 256 + gp0 + tx] * 1024.f;
        }
        __syncthreads();
#pragma unroll
        for (int r = 0; r < 4; r++) {
            int gp = gp0 + ty + r * 8;
            g_Ct[(size_t)aq * 65536 + (size_t)gp * 256 + g0 + tx] =
                __float2half_rn(ts[tx][ty + r * 8]);
        }
    }
}

// ---- reduce Gram partials (6 chunks, 3 tiles) + mirror + fp16 ---------------
__global__ void k_reduceG()
{
    GDC_WAIT();     // s1 complete
    GDC_LAUNCH();   // let s23 launch + prefetch W under our execution

    __shared__ float s[32][33];
    const int sub = blockIdx.x, t = blockIdx.y, bq = blockIdx.z;
    const int r0 = (sub >> 2) * 32, c0 = (sub & 3) * 32;
    const int tx = threadIdx.x & 31, ty = threadIdx.x >> 5;

    const int br = (t == 2) ? 128 : 0;
    const int bc = (t == 0) ? 0 : 128;
    float v[4];
#pragma unroll
    for (int k = 0; k < 4; k++) {
        const int r = r0 + ty + k * 8;
        float a = 0.f;
#pragma unroll
        for (int ch = 0; ch < 6; ch++)
            a += g_Gpart[(size_t)((ch * 8 + bq) * 3 + t) * 16384 + r * 128 + c0 + tx];
        v[k] = a;
        s[ty + k * 8][tx] = a;
    }
#pragma unroll
    for (int k = 0; k < 4; k++)
        g_G[(size_t)bq * 65536 + (size_t)(br + r0 + ty + k * 8) * 256 + bc + c0 + tx] =
            __float2half_rn(v[k]);
    if (t == 1) {
        __syncthreads();
#pragma unroll
        for (int k = 0; k < 4; k++)
            g_G[(size_t)bq * 65536 + (size_t)(128 + c0 + ty + k * 8) * 256 + r0 + tx] =
                __float2half_rn(s[tx][ty + k * 8]);
    }
}

// ---- reduce Pq over q + transpose + descale 2^-10 + fp16 --------------------
__global__ void k_reduceP()
{
    GDC_WAIT();     // s23 complete
    GDC_LAUNCH();   // let s4 launch + prefetch A under our execution

    __shared__ float t[32][33];
    const int ba = blockIdx.z, b = ba >> 2, a = ba & 3;
    const int e0 = blockIdx.y * 32, gp0 = blockIdx.x * 32;
    const int tx = threadIdx.x & 31, ty = threadIdx.x >> 5;
#pragma unroll
    for (int r = 0; r < 4; r++) {
        const int e = e0 + ty + r * 8;
        float s = 0.f;
#pragma unroll
        for (int q = 0; q < 4; q++)
            s += g_Pq[(size_t)(b * 16 + a * 4 + q) * 65536 + (size_t)e * 256 + gp0 + tx];
        t[ty + r * 8][tx] = s;
    }
    __syncthreads();
    const float ds = 1.0f / 1024.0f;
#pragma unroll
    for (int r = 0; r < 4; r++) {
        const int gp = gp0 + ty + r * 8;
        g_Pt[(size_t)ba * 65536 + (size_t)gp * 256 + e0 + tx] =
            __float2half_rn(t[tx][ty + r * 8] * ds);
    }
}

// ============================================================================
// s1 stage kernel
// ============================================================================
__global__ void __launch_bounds__(256)
k_s1()  // Gram, symmetric: grid (tile 3, chunk 6, bq 8) = 144 CTAs
{
    GDC_WAIT();     // conv complete
    GDC_LAUNCH();   // let reduceG launch under our execution

    const int t  = blockIdx.x;
    const int ch = blockIdx.y, bq = blockIdx.z;
    const int mt = (t == 2) ? 1 : 0;
    const int nt = (t == 0) ? 0 : 1;
    const int k0 = (ch < 4) ? ch * 384 : 1536 + (ch - 4) * 256;
    const int K  = (ch < 4) ? 384 : 256;

    size_t xo = (size_t)bq * 524288;
    const __half* A = g_Xt + xo + (size_t)mt * 128 * 2048 + k0;
    const __half* B = g_Xt + xo + (size_t)nt * 128 * 2048 + k0;
    float* Cf = g_Gpart + (size_t)((ch * 8 + bq) * 3 + t) * 16384;
    gemm128(A, 2048, B, 2048, K, Cf, 128);
}

// ============================================================================
extern "C" void kernel_launch(void* const* d_in, const int* in_sizes, int n_in,
                              void* d_out, int out_size)
{
    const float* hidden    = (const float*)d_in[0];  // [2,2048,1024]
    const float* queries   = (const float*)d_in[1];  // [4,256,1024]
    const float* combiners = (const float*)d_in[2];  // [4,1024,256]
    float* out = (float*)d_out;
    (void)in_sizes; (void)n_in; (void)out_size;

    cudaFuncSetAttribute(k_s1,  cudaFuncAttributeMaxDynamicSharedMemorySize, SMEM_G);
    cudaFuncSetAttribute(k_s23, cudaFuncAttributeMaxDynamicSharedMemorySize, SMEM_23);
    cudaFuncSetAttribute(k_s4,  cudaFuncAttributeMaxDynamicSharedMemorySize, SMEM_S4);

    k_conv<<<6144, 256>>>(hidden, queries, combiners);

    cudaLaunchAttribute at;
    at.id = cudaLaunchAttributeProgrammaticStreamSerialization;
    at.val.programmaticStreamSerializationAllowed = 1;

    {
        cudaLaunchConfig_t cfg = {};
        cfg.gridDim = dim3(3, 6, 8); cfg.blockDim = dim3(256, 1, 1);
        cfg.dynamicSmemBytes = SMEM_G; cfg.stream = 0;
        cfg.attrs = &at; cfg.numAttrs = 1;
        cudaLaunchKernelEx(&cfg, k_s1);
    }
    {
        cudaLaunchConfig_t cfg = {};
        cfg.gridDim = dim3(16, 3, 8); cfg.blockDim = dim3(256, 1, 1);
        cfg.dynamicSmemBytes = 0; cfg.stream = 0;
        cfg.attrs = &at; cfg.numAttrs = 1;
        cudaLaunchKernelEx(&cfg, k_reduceG);
    }
    {
        cudaLaunchConfig_t cfg = {};
        cfg.gridDim = dim3(4, 1, 32); cfg.blockDim = dim3(256, 1, 1);
        cfg.dynamicSmemBytes = SMEM_23; cfg.stream = 0;
        cfg.attrs = &at; cfg.numAttrs = 1;
        cudaLaunchKernelEx(&cfg, k_s23);
    }
    {
        cudaLaunchConfig_t cfg = {};
        cfg.gridDim = dim3(8, 8, 8); cfg.blockDim = dim3(256, 1, 1);
        cfg.dynamicSmemBytes = 0; cfg.stream = 0;
        cfg.attrs = &at; cfg.numAttrs = 1;
        cudaLaunchKernelEx(&cfg, k_reduceP);
    }
    {
        cudaLaunchConfig_t cfg = {};
        cfg.gridDim = dim3(16, 1, 8); cfg.blockDim = dim3(256, 1, 1);
        cfg.dynamicSmemBytes = SMEM_S4; cfg.stream = 0;
        cfg.attrs = &at; cfg.numAttrs = 1;
        cudaLaunchKernelEx(&cfg, k_s4, out);
    }
}

// round 14
// speedup vs baseline: 1.6285x; 1.0267x over previous
#include <cuda_runtime.h>
#include <cuda_fp16.h>
#include <cstdint>

// ============================================================================
// DenseAttention via Gram reassociation (R11 math, rel_err 5.2486e-4):
//   G = Xt Xt^T (sym, 3/4 tiles) ; T = Ws@G ; Pq = T@Ct^T ; P = 2^-10 sum_q Pq
//   out = 2^-10 * Xnt @ P
// R14: conv split. conv_x (hidden->Xt/Xnt) feeds s1; conv_wc (W/C, input-only)
// runs CONCURRENTLY with s1 via PDL-attr launch with no wait. reduceG launched
// WITHOUT PDL attr => waits all predecessors (s1 + conv_wc), preserving the
// transitive-completion guarantee for s23's pre-wait W prefetch.
// s4 now prefetches BOTH A chunks pre-wait.
// ============================================================================

#define HH 65536

__device__ __align__(256) __half g_Xt[8 * 256 * 2048];      // [bq][f][t]
__device__ __align__(256) __half g_Xnt[2 * 2048 * 1024];    // [b][t][e]
__device__ __align__(256) __half g_Wc[16 * HH];             // [aq][e][f] *1024
__device__ __align__(256) __half g_Ct[16 * HH];             // [aq][g'][g] *1024
__device__ __align__(256) float  g_Gpart[6 * 8 * 3 * 16384];
__device__ __align__(256) __half g_G[8 * HH];               // [bq][f][g]
__device__ __align__(256) float  g_Pq[32 * HH];             // [baq][e][g']
__device__ __align__(256) __half g_Pt[8 * HH];              // [ba][g'][e]

// ---------------- PTX helpers ------------------------------------------------
__device__ __forceinline__ uint32_t smem_u32(const void* p) {
    uint32_t a;
    asm("{ .reg .u64 t; cvta.to.shared.u64 t, %1; cvt.u32.u64 %0, t; }" : "=r"(a) : "l"(p));
    return a;
}
__device__ __forceinline__ void cpa16(uint32_t s, const void* g) {
    asm volatile("cp.async.cg.shared.global [%0], [%1], 16;" :: "r"(s), "l"(g));
}
#define CP_COMMIT() asm volatile("cp.async.commit_group;" ::: "memory")
#define CP_WAIT(n)  asm volatile("cp.async.wait_group %0;" :: "n"(n) : "memory")

#define GDC_WAIT()   asm volatile("griddepcontrol.wait;" ::: "memory")
#define GDC_LAUNCH() asm volatile("griddepcontrol.launch_dependents;")

#define LDSM_X4(r, addr) \
    asm volatile("ldmatrix.sync.aligned.m8n8.x4.shared.b16 {%0,%1,%2,%3}, [%4];" \
        : "=r"((r)[0]), "=r"((r)[1]), "=r"((r)[2]), "=r"((r)[3]) : "r"(addr))

#define MMA_F16(d, a, b0, b1) \
    asm volatile("mma.sync.aligned.m16n8k16.row.col.f32.f16.f16.f32 " \
        "{%0,%1,%2,%3}, {%4,%5,%6,%7}, {%8,%9}, {%0,%1,%2,%3};" \
        : "+f"((d)[0]), "+f"((d)[1]), "+f"((d)[2]), "+f"((d)[3]) \
        : "r"((a)[0]), "r"((a)[1]), "r"((a)[2]), "r"((a)[3]), "r"(b0), "r"(b1))

__device__ __forceinline__ uint2 pack4H(float4 v) {
    union { __half b[4]; uint2 u; } Hq;
    Hq.b[0] = __float2half_rn(v.x); Hq.b[1] = __float2half_rn(v.y);
    Hq.b[2] = __float2half_rn(v.z); Hq.b[3] = __float2half_rn(v.w);
    return Hq.u;
}

// ============================================================================
// Generic 128x128 tile GEMM (s1): 256 threads, 8 warps 4Mx2N (32x64 warp
// tile), BK=128 double-buffered cp.async, fp16 single-pass, fp32 accum.
// ============================================================================
#define ROWB   272
#define S1_B   34816
#define S1_BUF 69632
#define SMEM_G (2 * S1_BUF)

__device__ __forceinline__ void gemm128(
    const __half* __restrict__ A, int lda,
    const __half* __restrict__ B, int ldb,
    int K, float* __restrict__ Cf, int ldc)
{
    extern __shared__ char smem[];
    const uint32_t sb  = smem_u32(smem);
    const int tid  = threadIdx.x;
    const int lane = tid & 31;
    const int wid  = tid >> 5;
    const int m0   = (wid >> 1) * 32;
    const int n0   = (wid & 1) * 64;

    const uint32_t aoff = (uint32_t)(m0 + (lane & 15)) * ROWB + ((lane >> 4) << 4);
    const uint32_t boff = (uint32_t)(n0 + ((lane >> 4) << 3) + (lane & 7)) * ROWB
                        + ((lane & 8) ? 16u : 0u);

    float acc[2][8][4];
#pragma unroll
    for (int i = 0; i < 2; i++)
#pragma unroll
        for (int j = 0; j < 8; j++)
#pragma unroll
            for (int r = 0; r < 4; r++) acc[i][j][r] = 0.0f;

    auto load_chunk = [&](int c) {
        const uint32_t bo = sb + (uint32_t)(c & 1) * S1_BUF;
        const int k0 = c << 7;
#pragma unroll
        for (int i = 0; i < 8; i++) {
            int v = i * 256 + tid;
            int r = v >> 4, j = v & 15;
            uint32_t so = (uint32_t)r * ROWB + (uint32_t)j * 16;
            cpa16(bo + so, A + (size_t)r * lda + k0 + j * 8);
            cpa16(bo + S1_B + so, B + (size_t)r * ldb + k0 + j * 8);
        }
    };

    const int NC = K >> 7;
    load_chunk(0);
    CP_COMMIT();

#pragma unroll 1
    for (int c = 0; c < NC; c++) {
        if (c < NC - 1) { load_chunk(c + 1); CP_COMMIT(); CP_WAIT(1); }
        else            { CP_WAIT(0); }
        __syncthreads();

        const uint32_t bo = sb + (uint32_t)(c & 1) * S1_BUF;
        const uint32_t aP = bo + aoff;
        const uint32_t bP = bo + S1_B + boff;

#pragma unroll
        for (int ks = 0; ks < 8; ks++) {
            const uint32_t ko = (uint32_t)ks * 32;
            uint32_t a0[4], a1[4];
            LDSM_X4(a0, aP + ko);
            LDSM_X4(a1, aP + 16 * ROWB + ko);
            uint32_t br[4][4];
#pragma unroll
            for (int p = 0; p < 4; p++)
                LDSM_X4(br[p], bP + (uint32_t)p * 16 * ROWB + ko);
#pragma unroll
            for (int j = 0; j < 8; j++)
                MMA_F16(acc[0][j], a0, br[j >> 1][(j & 1) * 2], br[j >> 1][(j & 1) * 2 + 1]);
#pragma unroll
            for (int j = 0; j < 8; j++)
                MMA_F16(acc[1][j], a1, br[j >> 1][(j & 1) * 2], br[j >> 1][(j & 1) * 2 + 1]);
        }
        __syncthreads();
    }

    const int rr = lane >> 2;
    const int cc = (lane & 3) * 2;
#pragma unroll
    for (int i = 0; i < 2; i++)
#pragma unroll
        for (int j = 0; j < 8; j++) {
            const int row = m0 + i * 16 + rr;
            const int col = n0 + j * 8 + cc;
            float* p = Cf + (size_t)row * ldc + col;
            *(float2*)p = make_float2(acc[i][j][0], acc[i][j][1]);
            *(float2*)(p + (size_t)8 * ldc) = make_float2(acc[i][j][2], acc[i][j][3]);
        }
}

// ============================================================================
// FUSED s2+s3 kernel (unchanged from R13)
// ============================================================================
#define BUF23   87040
#define B23_OFF 17408
#define T23_OFF 174080
#define ROWB2   528
#define SMEM_23 207872

__global__ void __launch_bounds__(256)
k_s23()  // grid (et 4, 1, baq 32) = 128 CTAs
{
    extern __shared__ char smem[];
    const uint32_t sb  = smem_u32(smem);
    const int tid  = threadIdx.x;
    const int lane = tid & 31;
    const int wid  = tid >> 5;
    const int m0   = (wid & 1) * 32;
    const int n0   = (wid >> 1) * 64;
    const int et   = blockIdx.x;
    const int baq  = blockIdx.z;
    const int b = baq >> 4, a = (baq >> 2) & 3, q = baq & 3;
    const int aq = a * 4 + q, bq = b * 4 + q;

    const __half* Aw = g_Wc + (size_t)aq * 65536 + (size_t)et * 64 * 256;
    const __half* Bg = g_G  + (size_t)bq * 65536;
    const __half* Bc = g_Ct + (size_t)aq * 65536;

    // ---- pre-wait prefetch: W chunks 0/1 (conv_wc complete: reduceG started
    // after conv_wc finished, and we launch at reduceG's signal) -------------
#pragma unroll
    for (int c = 0; c < 2; c++) {
        const uint32_t bo = sb + (uint32_t)c * BUF23;
        const int k0 = c << 7;
#pragma unroll
        for (int i = 0; i < 4; i++) {
            int v = i * 256 + tid;
            int r = v >> 4, j = v & 15;
            cpa16(bo + (uint32_t)r * ROWB + (uint32_t)j * 16,
                  Aw + (size_t)r * 256 + k0 + j * 8);
        }
    }
    CP_COMMIT();

    GDC_WAIT();     // reduceG (G producer) complete
    GDC_LAUNCH();

    const uint32_t aoff  = (uint32_t)(m0 + (lane & 15)) * ROWB + ((lane >> 4) << 4);
    const uint32_t aoff2 = (uint32_t)(m0 + (lane & 15)) * ROWB2 + ((lane >> 4) << 4);
    const uint32_t boff  = (uint32_t)(n0 + ((lane >> 4) << 3) + (lane & 7)) * ROWB
                         + ((lane & 8) ? 16u : 0u);
    const int rr = lane >> 2;
    const int cc = (lane & 3) * 2;

    float acc[2][8][4];

    auto load_B = [&](int c, const __half* B) {
        const uint32_t bo = sb + (uint32_t)(c & 1) * BUF23 + B23_OFF;
        const int k0 = c << 7;
#pragma unroll
        for (int i = 0; i < 16; i++) {
            int v = i * 256 + tid;
            int r = v >> 4, j = v & 15;
            cpa16(bo + (uint32_t)r * ROWB + (uint32_t)j * 16,
                  B + (size_t)r * 256 + k0 + j * 8);
        }
    };
    auto zero_acc = [&]() {
#pragma unroll
        for (int i = 0; i < 2; i++)
#pragma unroll
            for (int j = 0; j < 8; j++)
#pragma unroll
                for (int r = 0; r < 4; r++) acc[i][j][r] = 0.0f;
    };
    auto mma_chunk = [&](uint32_t aP, uint32_t arowb, uint32_t bP) {
#pragma unroll
        for (int ks = 0; ks < 8; ks++) {
            const uint32_t ko = (uint32_t)ks * 32;
            uint32_t a0[4], a1[4];
            LDSM_X4(a0, aP + ko);
            LDSM_X4(a1, aP + 16 * arowb + ko);
            uint32_t br[4][4];
#pragma unroll
            for (int p = 0; p < 4; p++)
                LDSM_X4(br[p], bP + (uint32_t)p * 16 * ROWB + ko);
#pragma unroll
            for (int j = 0; j < 8; j++)
                MMA_F16(acc[0][j], a0, br[j >> 1][(j & 1) * 2], br[j >> 1][(j & 1) * 2 + 1]);
#pragma unroll
            for (int j = 0; j < 8; j++)
                MMA_F16(acc[1][j], a1, br[j >> 1][(j & 1) * 2], br[j >> 1][(j & 1) * 2 + 1]);
        }
    };

    // phase 1: T = Ws @ G
    zero_acc();
    load_B(0, Bg); CP_COMMIT();
    load_B(1, Bg); CP_COMMIT();
    CP_WAIT(1);
    __syncthreads();
    mma_chunk(sb + aoff, ROWB, sb + B23_OFF + boff);
    __syncthreads();
    load_B(0, Bc); CP_COMMIT();
    CP_WAIT(1);
    __syncthreads();
    mma_chunk(sb + BUF23 + aoff, ROWB, sb + BUF23 + B23_OFF + boff);
    __syncthreads();
    load_B(1, Bc); CP_COMMIT();

    // T epilogue -> SMEM fp16 (pitch 528B)
    {
        char* Tb = smem + T23_OFF;
#pragma unroll
        for (int i = 0; i < 2; i++)
#pragma unroll
            for (int j = 0; j < 8; j++) {
                const int row = m0 + i * 16 + rr;
                const int col = n0 + j * 8 + cc;
                *(__half2*)(Tb + (size_t)row * ROWB2 + col * 2) =
                    __halves2half2(__float2half_rn(acc[i][j][0]), __float2half_rn(acc[i][j][1]));
                *(__half2*)(Tb + (size_t)(row + 8) * ROWB2 + col * 2) =
                    __halves2half2(__float2half_rn(acc[i][j][2]), __float2half_rn(acc[i][j][3]));
            }
    }

    // phase 2: Pq = T @ Ct^T
    zero_acc();
    CP_WAIT(1);
    __syncthreads();
    mma_chunk(sb + T23_OFF + aoff2, ROWB2, sb + B23_OFF + boff);
    CP_WAIT(0);
    __syncthreads();
    mma_chunk(sb + T23_OFF + aoff2 + 256, ROWB2, sb + BUF23 + B23_OFF + boff);

    float* Cf = g_Pq + (size_t)baq * 65536 + (size_t)et * 64 * 256;
#pragma unroll
    for (int i = 0; i < 2; i++)
#pragma unroll
        for (int j = 0; j < 8; j++) {
            const int row = m0 + i * 16 + rr;
            const int col = n0 + j * 8 + cc;
            float* p = Cf + (size_t)row * 256 + col;
            *(float2*)p = make_float2(acc[i][j][0], acc[i][j][1]);
            *(float2*)(p + 8 * 256) = make_float2(acc[i][j][2], acc[i][j][3]);
        }
}

// ============================================================================
// s4: 128x256 tile, BK=128, single wave. BOTH A chunks prefetched pre-wait.
// ============================================================================
#define S4_B    34816
#define S4_BUF  104448
#define SMEM_S4 208896

__global__ void __launch_bounds__(256)
k_s4(float* __restrict__ out)   // grid (16, 1, 8) = 128 CTAs
{
    extern __shared__ char smem[];
    const uint32_t sb  = smem_u32(smem);
    const int tid  = threadIdx.x;
    const int lane = tid & 31;
    const int wid  = tid >> 5;
    const int mw   = (wid >> 2) * 64;
    const int nw   = (wid & 3) * 64;
    const int mt = blockIdx.x, ba = blockIdx.z;
    const int b = ba >> 2, a = ba & 3;

    const __half* A = g_Xnt + (size_t)b * 2097152 + (size_t)mt * 128 * 1024 + a * 256;
    const __half* B = g_Pt + (size_t)ba * 65536;
    float* Cf = out + (size_t)b * 2097152 + (size_t)mt * 128 * 1024 + a * 256;

    // ---- pre-wait prefetch: A chunk0 -> buf0.A, chunk1 -> buf1.A -----------
#pragma unroll
    for (int c = 0; c < 2; c++) {
        const uint32_t bo = sb + (uint32_t)c * S4_BUF;
        const int k0 = c << 7;
#pragma unroll
        for (int i = 0; i < 8; i++) {
            int v = i * 256 + tid;
            int r = v >> 4, j = v & 15;
            cpa16(bo + (uint32_t)r * ROWB + (uint32_t)j * 16,
                  A + (size_t)r * 1024 + k0 + j * 8);
        }
    }
    CP_COMMIT();                                   // {A0A1}

    GDC_WAIT();                                    // reduceP (Pt producer) done

    const uint32_t aoff = (uint32_t)(mw + (lane & 15)) * ROWB + ((lane >> 4) << 4);
    const uint32_t boff = (uint32_t)(nw + ((lane >> 4) << 3) + (lane & 7)) * ROWB
                        + ((lane & 8) ? 16u : 0u);

    float acc[4][8][4];
#pragma unroll
    for (int i = 0; i < 4; i++)
#pragma unroll
        for (int j = 0; j < 8; j++)
#pragma unroll
            for (int r = 0; r < 4; r++) acc[i][j][r] = 0.0f;

    // B c0
#pragma unroll
    for (int i = 0; i < 16; i++) {
        int v = i * 256 + tid;
        int r = v >> 4, j = v & 15;
        cpa16(sb + S4_B + (uint32_t)r * ROWB + (uint32_t)j * 16,
              B + (size_t)r * 256 + j * 8);
    }
    CP_COMMIT();                                   // {A0A1},{B0}
    // B c1
#pragma unroll
    for (int i = 0; i < 16; i++) {
        int v = i * 256 + tid;
        int r = v >> 4, j = v & 15;
        cpa16(sb + S4_BUF + S4_B + (uint32_t)r * ROWB + (uint32_t)j * 16,
              B + (size_t)r * 256 + 128 + j * 8);
    }
    CP_COMMIT();                                   // {A0A1},{B0},{B1}

#pragma unroll 1
    for (int c = 0; c < 2; c++) {
        if (c == 0) CP_WAIT(1);                    // A0A1 + B0 done
        else        CP_WAIT(0);
        __syncthreads();
        const uint32_t bo = sb + (uint32_t)c * S4_BUF;
        const uint32_t aP = bo + aoff;
        const uint32_t bP = bo + S4_B + boff;
#pragma unroll
        for (int ks = 0; ks < 8; ks++) {
            const uint32_t ko = (uint32_t)ks * 32;
            uint32_t af[4][4];
#pragma unroll
            for (int i = 0; i < 4; i++)
                LDSM_X4(af[i], aP + (uint32_t)i * 16 * ROWB + ko);
            uint32_t br[4][4];
#pragma unroll
            for (int p = 0; p < 4; p++)
                LDSM_X4(br[p], bP + (uint32_t)p * 16 * ROWB + ko);
#pragma unroll
            for (int i = 0; i < 4; i++)
#pragma unroll
                for (int j = 0; j < 8; j++)
                    MMA_F16(acc[i][j], af[i], br[j >> 1][(j & 1) * 2], br[j >> 1][(j & 1) * 2 + 1]);
        }
        __syncthreads();
    }

    const int rr = lane >> 2;
    const int cc = (lane & 3) * 2;
    const float ds = 1.0f / 1024.0f;
#pragma unroll
    for (int i = 0; i < 4; i++)
#pragma unroll
        for (int j = 0; j < 8; j++) {
            const int row = mw + i * 16 + rr;
            const int col = nw + j * 8 + cc;
            float* p = Cf + (size_t)row * 1024 + col;
            *(float2*)p = make_float2(acc[i][j][0] * ds, acc[i][j][1] * ds);
            *(float2*)(p + (size_t)8 * 1024) =
                make_float2(acc[i][j][2] * ds, acc[i][j][3] * ds);
        }
}

// ============================================================================
// conv_x: hidden -> Xt (transposed) + Xnt (natural), grid 4096 x 256
// ============================================================================
__global__ void k_conv_x(const float* __restrict__ hid)
{
    __shared__ float ts[32][33];
    const int blk = blockIdx.x;
    const int tid = threadIdx.x;

    int fb = blk & 7, tb = (blk >> 3) & 63, bq = blk >> 9;
    int b = bq >> 2, q = bq & 3;
    int t0 = tb * 32, f0 = fb * 32;
    int tx = tid & 31, ty = tid >> 5;
#pragma unroll
    for (int r = 0; r < 4; r++) {
        int tt = t0 + ty + r * 8;
        float v = hid[(size_t)b * 2097152 + (size_t)tt * 1024 + q * 256 + f0 + tx];
        ts[ty + r * 8][tx] = v;
        g_Xnt[(size_t)b * 2097152 + (size_t)tt * 1024 + q * 256 + f0 + tx] =
            __float2half_rn(v);
    }
    __syncthreads();
#pragma unroll
    for (int r = 0; r < 4; r++) {
        int f = f0 + ty + r * 8;
        g_Xt[(size_t)bq * 524288 + (size_t)f * 2048 + t0 + tx] =
            __float2half_rn(ts[tx][ty + r * 8]);
    }
}

// ============================================================================
// conv_wc: queries/combiners -> Wc / Ct, grid 2048 x 256.
// Launched WITH the PDL attribute AFTER s1 and fires no wait: it runs
// concurrently with s1 (reads only harness inputs; writes only Wc/Ct, first
// consumed by s23). reduceG (non-PDL) waits for its completion.
// ============================================================================
__global__ void k_conv_wc(const float* __restrict__ qr,
                          const float* __restrict__ cb)
{
    __shared__ float ts[32][33];
    const int blk = blockIdx.x;
    const int tid = threadIdx.x;

    if (blk < 1024) {
        int o4 = blk * 256 + tid;                        // 262144 float4s
        int aq = o4 >> 14;
        int rem = (o4 << 2) & 65535;
        int e = rem >> 8, f = rem & 255;
        int a = aq >> 2, q = aq & 3;
        float4 v = *(const float4*)(qr + (size_t)a * 262144 + (size_t)e * 1024 + q * 256 + f);
        v.x *= 1024.f; v.y *= 1024.f; v.z *= 1024.f; v.w *= 1024.f;
        ((uint2*)g_Wc)[o4] = pack4H(v);
    } else {
        int i = blk - 1024;                              // 8 x 8 x 16
        int gpb = i & 7, gb = (i >> 3) & 7, aq = i >> 6;
        int a = aq >> 2, q = aq & 3;
        int g0 = gb * 32, gp0 = gpb * 32;
        int tx = tid & 31, ty = tid >> 5;
#pragma unroll
        for (int r = 0; r < 4; r++) {
            int g = g0 + ty + r * 8;
            ts[ty + r * 8][tx] =
                cb[(size_t)a * 262144 + (size_t)(q * 256 + g) * 256 + gp0 + tx] * 1024.f;
        }
        __syncthreads();
#pragma unroll
        for (int r = 0; r < 4; r++) {
            int gp = gp0 + ty + r * 8;
            g_Ct[(size_t)aq * 65536 + (size_t)gp * 256 + g0 + tx] =
                __float2half_rn(ts[tx][ty + r * 8]);
        }
    }
}

// ---- reduce Gram partials: launched WITHOUT PDL attr (waits s1 + conv_wc) ---
__global__ void k_reduceG()
{
    GDC_LAUNCH();   // let s23 launch + prefetch W under our execution

    __shared__ float s[32][33];
    const int sub = blockIdx.x, t = blockIdx.y, bq = blockIdx.z;
    const int r0 = (sub >> 2) * 32, c0 = (sub & 3) * 32;
    const int tx = threadIdx.x & 31, ty = threadIdx.x >> 5;

    const int br = (t == 2) ? 128 : 0;
    const int bc = (t == 0) ? 0 : 128;
    float v[4];
#pragma unroll
    for (int k = 0; k < 4; k++) {
        const int r = r0 + ty + k * 8;
        float a = 0.f;
#pragma unroll
        for (int ch = 0; ch < 6; ch++)
            a += g_Gpart[(size_t)((ch * 8 + bq) * 3 + t) * 16384 + r * 128 + c0 + tx];
        v[k] = a;
        s[ty + k * 8][tx] = a;
    }
#pragma unroll
    for (int k = 0; k < 4; k++)
        g_G[(size_t)bq * 65536 + (size_t)(br + r0 + ty + k * 8) * 256 + bc + c0 + tx] =
            __float2half_rn(v[k]);
    if (t == 1) {
        __syncthreads();
#pragma unroll
        for (int k = 0; k < 4; k++)
            g_G[(size_t)bq * 65536 + (size_t)(128 + c0 + ty + k * 8) * 256 + r0 + tx] =
                __float2half_rn(s[tx][ty + k * 8]);
    }
}

// ---- reduce Pq over q + transpose + descale 2^-10 + fp16 --------------------
__global__ void k_reduceP()
{
    GDC_WAIT();     // s23 complete
    GDC_LAUNCH();   // let s4 launch + prefetch A under our execution

    __shared__ float t[32][33];
    const int ba = blockIdx.z, b = ba >> 2, a = ba & 3;
    const int e0 = blockIdx.y * 32, gp0 = blockIdx.x * 32;
    const int tx = threadIdx.x & 31, ty = threadIdx.x >> 5;
#pragma unroll
    for (int r = 0; r < 4; r++) {
        const int e = e0 + ty + r * 8;
        float s = 0.f;
#pragma unroll
        for (int q = 0; q < 4; q++)
            s += g_Pq[(size_t)(b * 16 + a * 4 + q) * 65536 + (size_t)e * 256 + gp0 + tx];
        t[ty + r * 8][tx] = s;
    }
    __syncthreads();
    const float ds = 1.0f / 1024.0f;
#pragma unroll
    for (int r = 0; r < 4; r++) {
        const int gp = gp0 + ty + r * 8;
        g_Pt[(size_t)ba * 65536 + (size_t)gp * 256 + e0 + tx] =
            __float2half_rn(t[tx][ty + r * 8] * ds);
    }
}

// ============================================================================
// s1 stage kernel
// ============================================================================
__global__ void __launch_bounds__(256)
k_s1()  // Gram, symmetric: grid (tile 3, chunk 6, bq 8) = 144 CTAs
{
    GDC_WAIT();     // conv_x complete
    GDC_LAUNCH();   // let conv_wc launch + run under our execution

    const int t  = blockIdx.x;
    const int ch = blockIdx.y, bq = blockIdx.z;
    const int mt = (t == 2) ? 1 : 0;
    const int nt = (t == 0) ? 0 : 1;
    const int k0 = (ch < 4) ? ch * 384 : 1536 + (ch - 4) * 256;
    const int K  = (ch < 4) ? 384 : 256;

    size_t xo = (size_t)bq * 524288;
    const __half* A = g_Xt + xo + (size_t)mt * 128 * 2048 + k0;
    const __half* B = g_Xt + xo + (size_t)nt * 128 * 2048 + k0;
    float* Cf = g_Gpart + (size_t)((ch * 8 + bq) * 3 + t) * 16384;
    gemm128(A, 2048, B, 2048, K, Cf, 128);
}

// ============================================================================
extern "C" void kernel_launch(void* const* d_in, const int* in_sizes, int n_in,
                              void* d_out, int out_size)
{
    const float* hidden    = (const float*)d_in[0];  // [2,2048,1024]
    const float* queries   = (const float*)d_in[1];  // [4,256,1024]
    const float* combiners = (const float*)d_in[2];  // [4,1024,256]
    float* out = (float*)d_out;
    (void)in_sizes; (void)n_in; (void)out_size;

    cudaFuncSetAttribute(k_s1,  cudaFuncAttributeMaxDynamicSharedMemorySize, SMEM_G);
    cudaFuncSetAttribute(k_s23, cudaFuncAttributeMaxDynamicSharedMemorySize, SMEM_23);
    cudaFuncSetAttribute(k_s4,  cudaFuncAttributeMaxDynamicSharedMemorySize, SMEM_S4);

    k_conv_x<<<4096, 256>>>(hidden);

    cudaLaunchAttribute at;
    at.id = cudaLaunchAttributeProgrammaticStreamSerialization;
    at.val.programmaticStreamSerializationAllowed = 1;

    {   // s1: PDL after conv_x
        cudaLaunchConfig_t cfg = {};
        cfg.gridDim = dim3(3, 6, 8); cfg.blockDim = dim3(256, 1, 1);
        cfg.dynamicSmemBytes = SMEM_G; cfg.stream = 0;
        cfg.attrs = &at; cfg.numAttrs = 1;
        cudaLaunchKernelEx(&cfg, k_s1);
    }
    {   // conv_wc: PDL after s1 (s1 signals at start) => runs DURING s1
        cudaLaunchConfig_t cfg = {};
        cfg.gridDim = dim3(2048, 1, 1); cfg.blockDim = dim3(256, 1, 1);
        cfg.dynamicSmemBytes = 0; cfg.stream = 0;
        cfg.attrs = &at; cfg.numAttrs = 1;
        cudaLaunchKernelEx(&cfg, k_conv_wc, queries, combiners);
    }
    {   // reduceG: NO PDL attr => waits completion of s1 AND conv_wc
        cudaLaunchConfig_t cfg = {};
        cfg.gridDim = dim3(16, 3, 8); cfg.blockDim = dim3(256, 1, 1);
        cfg.dynamicSmemBytes = 0; cfg.stream = 0;
        cudaLaunchKernelEx(&cfg, k_reduceG);
    }
    {   // s23: PDL after reduceG (prefetches W pre-wait)
        cudaLaunchConfig_t cfg = {};
        cfg.gridDim = dim3(4, 1, 32); cfg.blockDim = dim3(256, 1, 1);
        cfg.dynamicSmemBytes = SMEM_23; cfg.stream = 0;
        cfg.attrs = &at; cfg.numAttrs = 1;
        cudaLaunchKernelEx(&cfg, k_s23);
    }
    {   // reduceP: PDL after s23
        cudaLaunchConfig_t cfg = {};
        cfg.gridDim = dim3(8, 8, 8); cfg.blockDim = dim3(256, 1, 1);
        cfg.dynamicSmemBytes = 0; cfg.stream = 0;
        cfg.attrs = &at; cfg.numAttrs = 1;
        cudaLaunchKernelEx(&cfg, k_reduceP);
    }
    {   // s4: PDL after reduceP (prefetches both A chunks pre-wait)
        cudaLaunchConfig_t cfg = {};
        cfg.gridDim = dim3(16, 1, 8); cfg.blockDim = dim3(256, 1, 1);
        cfg.dynamicSmemBytes = SMEM_S4; cfg.stream = 0;
        cfg.attrs = &at; cfg.numAttrs = 1;
        cudaLaunchKernelEx(&cfg, k_s4, out);
    }
}

// round 15
// speedup vs baseline: 1.6486x; 1.0124x over previous
#include <cuda_runtime.h>
#include <cuda_fp16.h>
#include <cstdint>

// ============================================================================
// DenseAttention via Gram reassociation (R11 math, rel_err 5.2486e-4):
//   G = Xt Xt^T (sym, 3/4 tiles) ; T = Ws@G ; Pq = T@Ct^T ; P = 2^-10 sum_q Pq
//   out = 2^-10 * Xnt @ P
// R14: conv split. conv_x (hidden->Xt/Xnt) feeds s1; conv_wc (W/C, input-only)
// runs CONCURRENTLY with s1 via PDL-attr launch with no wait. reduceG launched
// WITHOUT PDL attr => waits all predecessors (s1 + conv_wc), preserving the
// transitive-completion guarantee for s23's pre-wait W prefetch.
// s4 now prefetches BOTH A chunks pre-wait.
// ============================================================================

#define HH 65536

__device__ __align__(256) __half g_Xt[8 * 256 * 2048];      // [bq][f][t]
__device__ __align__(256) __half g_Xnt[2 * 2048 * 1024];    // [b][t][e]
__device__ __align__(256) __half g_Wc[16 * HH];             // [aq][e][f] *1024
__device__ __align__(256) __half g_Ct[16 * HH];             // [aq][g'][g] *1024
__device__ __align__(256) float  g_Gpart[6 * 8 * 3 * 16384];
__device__ __align__(256) __half g_G[8 * HH];               // [bq][f][g]
__device__ __align__(256) float  g_Pq[32 * HH];             // [baq][e][g']
__device__ __align__(256) __half g_Pt[8 * HH];              // [ba][g'][e]

// ---------------- PTX helpers ------------------------------------------------
__device__ __forceinline__ uint32_t smem_u32(const void* p) {
    uint32_t a;
    asm("{ .reg .u64 t; cvta.to.shared.u64 t, %1; cvt.u32.u64 %0, t; }" : "=r"(a) : "l"(p));
    return a;
}
__device__ __forceinline__ void cpa16(uint32_t s, const void* g) {
    asm volatile("cp.async.cg.shared.global [%0], [%1], 16;" :: "r"(s), "l"(g));
}
#define CP_COMMIT() asm volatile("cp.async.commit_group;" ::: "memory")
#define CP_WAIT(n)  asm volatile("cp.async.wait_group %0;" :: "n"(n) : "memory")

#define GDC_WAIT()   asm volatile("griddepcontrol.wait;" ::: "memory")
#define GDC_LAUNCH() asm volatile("griddepcontrol.launch_dependents;")

#define LDSM_X4(r, addr) \
    asm volatile("ldmatrix.sync.aligned.m8n8.x4.shared.b16 {%0,%1,%2,%3}, [%4];" \
        : "=r"((r)[0]), "=r"((r)[1]), "=r"((r)[2]), "=r"((r)[3]) : "r"(addr))

#define MMA_F16(d, a, b0, b1) \
    asm volatile("mma.sync.aligned.m16n8k16.row.col.f32.f16.f16.f32 " \
        "{%0,%1,%2,%3}, {%4,%5,%6,%7}, {%8,%9}, {%0,%1,%2,%3};" \
        : "+f"((d)[0]), "+f"((d)[1]), "+f"((d)[2]), "+f"((d)[3]) \
        : "r"((a)[0]), "r"((a)[1]), "r"((a)[2]), "r"((a)[3]), "r"(b0), "r"(b1))

__device__ __forceinline__ uint2 pack4H(float4 v) {
    union { __half b[4]; uint2 u; } Hq;
    Hq.b[0] = __float2half_rn(v.x); Hq.b[1] = __float2half_rn(v.y);
    Hq.b[2] = __float2half_rn(v.z); Hq.b[3] = __float2half_rn(v.w);
    return Hq.u;
}

// ============================================================================
// Generic 128x128 tile GEMM (s1): 256 threads, 8 warps 4Mx2N (32x64 warp
// tile), BK=128 double-buffered cp.async, fp16 single-pass, fp32 accum.
// ============================================================================
#define ROWB   272
#define S1_B   34816
#define S1_BUF 69632
#define SMEM_G (2 * S1_BUF)

__device__ __forceinline__ void gemm128(
    const __half* __restrict__ A, int lda,
    const __half* __restrict__ B, int ldb,
    int K, float* __restrict__ Cf, int ldc)
{
    extern __shared__ char smem[];
    const uint32_t sb  = smem_u32(smem);
    const int tid  = threadIdx.x;
    const int lane = tid & 31;
    const int wid  = tid >> 5;
    const int m0   = (wid >> 1) * 32;
    const int n0   = (wid & 1) * 64;

    const uint32_t aoff = (uint32_t)(m0 + (lane & 15)) * ROWB + ((lane >> 4) << 4);
    const uint32_t boff = (uint32_t)(n0 + ((lane >> 4) << 3) + (lane & 7)) * ROWB
                        + ((lane & 8) ? 16u : 0u);

    float acc[2][8][4];
#pragma unroll
    for (int i = 0; i < 2; i++)
#pragma unroll
        for (int j = 0; j < 8; j++)
#pragma unroll
            for (int r = 0; r < 4; r++) acc[i][j][r] = 0.0f;

    auto load_chunk = [&](int c) {
        const uint32_t bo = sb + (uint32_t)(c & 1) * S1_BUF;
        const int k0 = c << 7;
#pragma unroll
        for (int i = 0; i < 8; i++) {
            int v = i * 256 + tid;
            int r = v >> 4, j = v & 15;
            uint32_t so = (uint32_t)r * ROWB + (uint32_t)j * 16;
            cpa16(bo + so, A + (size_t)r * lda + k0 + j * 8);
            cpa16(bo + S1_B + so, B + (size_t)r * ldb + k0 + j * 8);
        }
    };

    const int NC = K >> 7;
    load_chunk(0);
    CP_COMMIT();

#pragma unroll 1
    for (int c = 0; c < NC; c++) {
        if (c < NC - 1) { load_chunk(c + 1); CP_COMMIT(); CP_WAIT(1); }
        else            { CP_WAIT(0); }
        __syncthreads();

        const uint32_t bo = sb + (uint32_t)(c & 1) * S1_BUF;
        const uint32_t aP = bo + aoff;
        const uint32_t bP = bo + S1_B + boff;

#pragma unroll
        for (int ks = 0; ks < 8; ks++) {
            const uint32_t ko = (uint32_t)ks * 32;
            uint32_t a0[4], a1[4];
            LDSM_X4(a0, aP + ko);
            LDSM_X4(a1, aP + 16 * ROWB + ko);
            uint32_t br[4][4];
#pragma unroll
            for (int p = 0; p < 4; p++)
                LDSM_X4(br[p], bP + (uint32_t)p * 16 * ROWB + ko);
#pragma unroll
            for (int j = 0; j < 8; j++)
                MMA_F16(acc[0][j], a0, br[j >> 1][(j & 1) * 2], br[j >> 1][(j & 1) * 2 + 1]);
#pragma unroll
            for (int j = 0; j < 8; j++)
                MMA_F16(acc[1][j], a1, br[j >> 1][(j & 1) * 2], br[j >> 1][(j & 1) * 2 + 1]);
        }
        __syncthreads();
    }

    const int rr = lane >> 2;
    const int cc = (lane & 3) * 2;
#pragma unroll
    for (int i = 0; i < 2; i++)
#pragma unroll
        for (int j = 0; j < 8; j++) {
            const int row = m0 + i * 16 + rr;
            const int col = n0 + j * 8 + cc;
            float* p = Cf + (size_t)row * ldc + col;
            *(float2*)p = make_float2(acc[i][j][0], acc[i][j][1]);
            *(float2*)(p + (size_t)8 * ldc) = make_float2(acc[i][j][2], acc[i][j][3]);
        }
}

// ============================================================================
// FUSED s2+s3 kernel (unchanged from R13)
// ============================================================================
#define BUF23   87040
#define B23_OFF 17408
#define T23_OFF 174080
#define ROWB2   528
#define SMEM_23 207872

__global__ void __launch_bounds__(256)
k_s23()  // grid (et 4, 1, baq 32) = 128 CTAs
{
    extern __shared__ char smem[];
    const uint32_t sb  = smem_u32(smem);
    const int tid  = threadIdx.x;
    const int lane = tid & 31;
    const int wid  = tid >> 5;
    const int m0   = (wid & 1) * 32;
    const int n0   = (wid >> 1) * 64;
    const int et   = blockIdx.x;
    const int baq  = blockIdx.z;
    const int b = baq >> 4, a = (baq >> 2) & 3, q = baq & 3;
    const int aq = a * 4 + q, bq = b * 4 + q;

    const __half* Aw = g_Wc + (size_t)aq * 65536 + (size_t)et * 64 * 256;
    const __half* Bg = g_G  + (size_t)bq * 65536;
    const __half* Bc = g_Ct + (size_t)aq * 65536;

    // ---- pre-wait prefetch: W chunks 0/1 (conv_wc complete: reduceG started
    // after conv_wc finished, and we launch at reduceG's signal) -------------
#pragma unroll
    for (int c = 0; c < 2; c++) {
        const uint32_t bo = sb + (uint32_t)c * BUF23;
        const int k0 = c << 7;
#pragma unroll
        for (int i = 0; i < 4; i++) {
            int v = i * 256 + tid;
            int r = v >> 4, j = v & 15;
            cpa16(bo + (uint32_t)r * ROWB + (uint32_t)j * 16,
                  Aw + (size_t)r * 256 + k0 + j * 8);
        }
    }
    CP_COMMIT();

    GDC_WAIT();     // reduceG (G producer) complete
    GDC_LAUNCH();

    const uint32_t aoff  = (uint32_t)(m0 + (lane & 15)) * ROWB + ((lane >> 4) << 4);
    const uint32_t aoff2 = (uint32_t)(m0 + (lane & 15)) * ROWB2 + ((lane >> 4) << 4);
    const uint32_t boff  = (uint32_t)(n0 + ((lane >> 4) << 3) + (lane & 7)) * ROWB
                         + ((lane & 8) ? 16u : 0u);
    const int rr = lane >> 2;
    const int cc = (lane & 3) * 2;

    float acc[2][8][4];

    auto load_B = [&](int c, const __half* B) {
        const uint32_t bo = sb + (uint32_t)(c & 1) * BUF23 + B23_OFF;
        const int k0 = c << 7;
#pragma unroll
        for (int i = 0; i < 16; i++) {
            int v = i * 256 + tid;
            int r = v >> 4, j = v & 15;
            cpa16(bo + (uint32_t)r * ROWB + (uint32_t)j * 16,
                  B + (size_t)r * 256 + k0 + j * 8);
        }
    };
    auto zero_acc = [&]() {
#pragma unroll
        for (int i = 0; i < 2; i++)
#pragma unroll
            for (int j = 0; j < 8; j++)
#pragma unroll
                for (int r = 0; r < 4; r++) acc[i][j][r] = 0.0f;
    };
    auto mma_chunk = [&](uint32_t aP, uint32_t arowb, uint32_t bP) {
#pragma unroll
        for (int ks = 0; ks < 8; ks++) {
            const uint32_t ko = (uint32_t)ks * 32;
            uint32_t a0[4], a1[4];
            LDSM_X4(a0, aP + ko);
            LDSM_X4(a1, aP + 16 * arowb + ko);
            uint32_t br[4][4];
#pragma unroll
            for (int p = 0; p < 4; p++)
                LDSM_X4(br[p], bP + (uint32_t)p * 16 * ROWB + ko);
#pragma unroll
            for (int j = 0; j < 8; j++)
                MMA_F16(acc[0][j], a0, br[j >> 1][(j & 1) * 2], br[j >> 1][(j & 1) * 2 + 1]);
#pragma unroll
            for (int j = 0; j < 8; j++)
                MMA_F16(acc[1][j], a1, br[j >> 1][(j & 1) * 2], br[j >> 1][(j & 1) * 2 + 1]);
        }
    };

    // phase 1: T = Ws @ G
    zero_acc();
    load_B(0, Bg); CP_COMMIT();
    load_B(1, Bg); CP_COMMIT();
    CP_WAIT(1);
    __syncthreads();
    mma_chunk(sb + aoff, ROWB, sb + B23_OFF + boff);
    __syncthreads();
    load_B(0, Bc); CP_COMMIT();
    CP_WAIT(1);
    __syncthreads();
    mma_chunk(sb + BUF23 + aoff, ROWB, sb + BUF23 + B23_OFF + boff);
    __syncthreads();
    load_B(1, Bc); CP_COMMIT();

    // T epilogue -> SMEM fp16 (pitch 528B)
    {
        char* Tb = smem + T23_OFF;
#pragma unroll
        for (int i = 0; i < 2; i++)
#pragma unroll
            for (int j = 0; j < 8; j++) {
                const int row = m0 + i * 16 + rr;
                const int col = n0 + j * 8 + cc;
                *(__half2*)(Tb + (size_t)row * ROWB2 + col * 2) =
                    __halves2half2(__float2half_rn(acc[i][j][0]), __float2half_rn(acc[i][j][1]));
                *(__half2*)(Tb + (size_t)(row + 8) * ROWB2 + col * 2) =
                    __halves2half2(__float2half_rn(acc[i][j][2]), __float2half_rn(acc[i][j][3]));
            }
    }

    // phase 2: Pq = T @ Ct^T
    zero_acc();
    CP_WAIT(1);
    __syncthreads();
    mma_chunk(sb + T23_OFF + aoff2, ROWB2, sb + B23_OFF + boff);
    CP_WAIT(0);
    __syncthreads();
    mma_chunk(sb + T23_OFF + aoff2 + 256, ROWB2, sb + BUF23 + B23_OFF + boff);

    float* Cf = g_Pq + (size_t)baq * 65536 + (size_t)et * 64 * 256;
#pragma unroll
    for (int i = 0; i < 2; i++)
#pragma unroll
        for (int j = 0; j < 8; j++) {
            const int row = m0 + i * 16 + rr;
            const int col = n0 + j * 8 + cc;
            float* p = Cf + (size_t)row * 256 + col;
            *(float2*)p = make_float2(acc[i][j][0], acc[i][j][1]);
            *(float2*)(p + 8 * 256) = make_float2(acc[i][j][2], acc[i][j][3]);
        }
}

// ============================================================================
// s4: 128x256 tile, BK=128, single wave. BOTH A chunks prefetched pre-wait.
// ============================================================================
#define S4_B    34816
#define S4_BUF  104448
#define SMEM_S4 208896

__global__ void __launch_bounds__(256)
k_s4(float* __restrict__ out)   // grid (16, 1, 8) = 128 CTAs
{
    extern __shared__ char smem[];
    const uint32_t sb  = smem_u32(smem);
    const int tid  = threadIdx.x;
    const int lane = tid & 31;
    const int wid  = tid >> 5;
    const int mw   = (wid >> 2) * 64;
    const int nw   = (wid & 3) * 64;
    const int mt = blockIdx.x, ba = blockIdx.z;
    const int b = ba >> 2, a = ba & 3;

    const __half* A = g_Xnt + (size_t)b * 2097152 + (size_t)mt * 128 * 1024 + a * 256;
    const __half* B = g_Pt + (size_t)ba * 65536;
    float* Cf = out + (size_t)b * 2097152 + (size_t)mt * 128 * 1024 + a * 256;

    // ---- pre-wait prefetch: A chunk0 -> buf0.A, chunk1 -> buf1.A -----------
#pragma unroll
    for (int c = 0; c < 2; c++) {
        const uint32_t bo = sb + (uint32_t)c * S4_BUF;
        const int k0 = c << 7;
#pragma unroll
        for (int i = 0; i < 8; i++) {
            int v = i * 256 + tid;
            int r = v >> 4, j = v & 15;
            cpa16(bo + (uint32_t)r * ROWB + (uint32_t)j * 16,
                  A + (size_t)r * 1024 + k0 + j * 8);
        }
    }
    CP_COMMIT();                                   // {A0A1}

    GDC_WAIT();                                    // reduceP (Pt producer) done

    const uint32_t aoff = (uint32_t)(mw + (lane & 15)) * ROWB + ((lane >> 4) << 4);
    const uint32_t boff = (uint32_t)(nw + ((lane >> 4) << 3) + (lane & 7)) * ROWB
                        + ((lane & 8) ? 16u : 0u);

    float acc[4][8][4];
#pragma unroll
    for (int i = 0; i < 4; i++)
#pragma unroll
        for (int j = 0; j < 8; j++)
#pragma unroll
            for (int r = 0; r < 4; r++) acc[i][j][r] = 0.0f;

    // B c0
#pragma unroll
    for (int i = 0; i < 16; i++) {
        int v = i * 256 + tid;
        int r = v >> 4, j = v & 15;
        cpa16(sb + S4_B + (uint32_t)r * ROWB + (uint32_t)j * 16,
              B + (size_t)r * 256 + j * 8);
    }
    CP_COMMIT();                                   // {A0A1},{B0}
    // B c1
#pragma unroll
    for (int i = 0; i < 16; i++) {
        int v = i * 256 + tid;
        int r = v >> 4, j = v & 15;
        cpa16(sb + S4_BUF + S4_B + (uint32_t)r * ROWB + (uint32_t)j * 16,
              B + (size_t)r * 256 + 128 + j * 8);
    }
    CP_COMMIT();                                   // {A0A1},{B0},{B1}

#pragma unroll 1
    for (int c = 0; c < 2; c++) {
        if (c == 0) CP_WAIT(1);                    // A0A1 + B0 done
        else        CP_WAIT(0);
        __syncthreads();
        const uint32_t bo = sb + (uint32_t)c * S4_BUF;
        const uint32_t aP = bo + aoff;
        const uint32_t bP = bo + S4_B + boff;
#pragma unroll
        for (int ks = 0; ks < 8; ks++) {
            const uint32_t ko = (uint32_t)ks * 32;
            uint32_t af[4][4];
#pragma unroll
            for (int i = 0; i < 4; i++)
                LDSM_X4(af[i], aP + (uint32_t)i * 16 * ROWB + ko);
            uint32_t br[4][4];
#pragma unroll
            for (int p = 0; p < 4; p++)
                LDSM_X4(br[p], bP + (uint32_t)p * 16 * ROWB + ko);
#pragma unroll
            for (int i = 0; i < 4; i++)
#pragma unroll
                for (int j = 0; j < 8; j++)
                    MMA_F16(acc[i][j], af[i], br[j >> 1][(j & 1) * 2], br[j >> 1][(j & 1) * 2 + 1]);
        }
        __syncthreads();
    }

    const int rr = lane >> 2;
    const int cc = (lane & 3) * 2;
    const float ds = 1.0f / 1024.0f;
#pragma unroll
    for (int i = 0; i < 4; i++)
#pragma unroll
        for (int j = 0; j < 8; j++) {
            const int row = mw + i * 16 + rr;
            const int col = nw + j * 8 + cc;
            float* p = Cf + (size_t)row * 1024 + col;
            *(float2*)p = make_float2(acc[i][j][0] * ds, acc[i][j][1] * ds);
            *(float2*)(p + (size_t)8 * 1024) =
                make_float2(acc[i][j][2] * ds, acc[i][j][3] * ds);
        }
}

// ============================================================================
// conv_x: hidden -> Xt (transposed) + Xnt (natural), grid 4096 x 256
// ============================================================================
__global__ void k_conv_x(const float* __restrict__ hid)
{
    __shared__ float ts[32][33];
    const int blk = blockIdx.x;
    const int tid = threadIdx.x;

    int fb = blk & 7, tb = (blk >> 3) & 63, bq = blk >> 9;
    int b = bq >> 2, q = bq & 3;
    int t0 = tb * 32, f0 = fb * 32;
    int tx = tid & 31, ty = tid >> 5;
#pragma unroll
    for (int r = 0; r < 4; r++) {
        int tt = t0 + ty + r * 8;
        float v = hid[(size_t)b * 2097152 + (size_t)tt * 1024 + q * 256 + f0 + tx];
        ts[ty + r * 8][tx] = v;
        g_Xnt[(size_t)b * 2097152 + (size_t)tt * 1024 + q * 256 + f0 + tx] =
            __float2half_rn(v);
    }
    __syncthreads();
#pragma unroll
    for (int r = 0; r < 4; r++) {
        int f = f0 + ty + r * 8;
        g_Xt[(size_t)bq * 524288 + (size_t)f * 2048 + t0 + tx] =
            __float2half_rn(ts[tx][ty + r * 8]);
    }
}

// ============================================================================
// conv_wc: queries/combiners -> Wc / Ct, grid 2048 x 256.
// Launched WITH the PDL attribute AFTER s1 and fires no wait: it runs
// concurrently with s1 (reads only harness inputs; writes only Wc/Ct, first
// consumed by s23). reduceG (non-PDL) waits for its completion.
// ============================================================================
__global__ void k_conv_wc(const float* __restrict__ qr,
                          const float* __restrict__ cb)
{
    __shared__ float ts[32][33];
    const int blk = blockIdx.x;
    const int tid = threadIdx.x;

    if (blk < 1024) {
        int o4 = blk * 256 + tid;                        // 262144 float4s
        int aq = o4 >> 14;
        int rem = (o4 << 2) & 65535;
        int e = rem >> 8, f = rem & 255;
        int a = aq >> 2, q = aq & 3;
        float4 v = *(const float4*)(qr + (size_t)a * 262144 + (size_t)e * 1024 + q * 256 + f);
        v.x *= 1024.f; v.y *= 1024.f; v.z *= 1024.f; v.w *= 1024.f;
        ((uint2*)g_Wc)[o4] = pack4H(v);
    } else {
        int i = blk - 1024;                              // 8 x 8 x 16
        int gpb = i & 7, gb = (i >> 3) & 7, aq = i >> 6;
        int a = aq >> 2, q = aq & 3;
        int g0 = gb * 32, gp0 = gpb * 32;
        int tx = tid & 31, ty = tid >> 5;
#pragma unroll
        for (int r = 0; r < 4; r++) {
            int g = g0 + ty + r * 8;
            ts[ty + r * 8][tx] =
                cb[(size_t)a * 262144 + (size_t)(q * 256 + g) * 256 + gp0 + tx] * 1024.f;
        }
        __syncthreads();
#pragma unroll
        for (int r = 0; r < 4; r++) {
            int gp = gp0 + ty + r * 8;
            g_Ct[(size_t)aq * 65536 + (size_t)gp * 256 + g0 + tx] =
                __float2half_rn(ts[tx][ty + r * 8]);
        }
    }
}

// ---- reduce Gram partials: launched WITHOUT PDL attr (waits s1 + conv_wc) ---
__global__ void k_reduceG()
{
    GDC_LAUNCH();   // let s23 launch + prefetch W under our execution

    __shared__ float s[32][33];
    const int sub = blockIdx.x, t = blockIdx.y, bq = blockIdx.z;
    const int r0 = (sub >> 2) * 32, c0 = (sub & 3) * 32;
    const int tx = threadIdx.x & 31, ty = threadIdx.x >> 5;

    const int br = (t == 2) ? 128 : 0;
    const int bc = (t == 0) ? 0 : 128;
    float v[4];
#pragma unroll
    for (int k = 0; k < 4; k++) {
        const int r = r0 + ty + k * 8;
        float a = 0.f;
#pragma unroll
        for (int ch = 0; ch < 6; ch++)
            a += g_Gpart[(size_t)((ch * 8 + bq) * 3 + t) * 16384 + r * 128 + c0 + tx];
        v[k] = a;
        s[ty + k * 8][tx] = a;
    }
#pragma unroll
    for (int k = 0; k < 4; k++)
        g_G[(size_t)bq * 65536 + (size_t)(br + r0 + ty + k * 8) * 256 + bc + c0 + tx] =
            __float2half_rn(v[k]);
    if (t == 1) {
        __syncthreads();
#pragma unroll
        for (int k = 0; k < 4; k++)
            g_G[(size_t)bq * 65536 + (size_t)(128 + c0 + ty + k * 8) * 256 + r0 + tx] =
                __float2half_rn(s[tx][ty + k * 8]);
    }
}

// ---- reduce Pq over q + transpose + descale 2^-10 + fp16 --------------------
__global__ void k_reduceP()
{
    GDC_WAIT();     // s23 complete
    GDC_LAUNCH();   // let s4 launch + prefetch A under our execution

    __shared__ float t[32][33];
    const int ba = blockIdx.z, b = ba >> 2, a = ba & 3;
    const int e0 = blockIdx.y * 32, gp0 = blockIdx.x * 32;
    const int tx = threadIdx.x & 31, ty = threadIdx.x >> 5;
#pragma unroll
    for (int r = 0; r < 4; r++) {
        const int e = e0 + ty + r * 8;
        float s = 0.f;
#pragma unroll
        for (int q = 0; q < 4; q++)
            s += g_Pq[(size_t)(b * 16 + a * 4 + q) * 65536 + (size_t)e * 256 + gp0 + tx];
        t[ty + r * 8][tx] = s;
    }
    __syncthreads();
    const float ds = 1.0f / 1024.0f;
#pragma unroll
    for (int r = 0; r < 4; r++) {
        const int gp = gp0 + ty + r * 8;
        g_Pt[(size_t)ba * 65536 + (size_t)gp * 256 + e0 + tx] =
            __float2half_rn(t[tx][ty + r * 8] * ds);
    }
}

// ============================================================================
// s1 stage kernel
// ============================================================================
__global__ void __launch_bounds__(256)
k_s1()  // Gram, symmetric: grid (tile 3, chunk 6, bq 8) = 144 CTAs
{
    GDC_WAIT();     // conv_x complete
    GDC_LAUNCH();   // let conv_wc launch + run under our execution

    const int t  = blockIdx.x;
    const int ch = blockIdx.y, bq = blockIdx.z;
    const int mt = (t == 2) ? 1 : 0;
    const int nt = (t == 0) ? 0 : 1;
    const int k0 = (ch < 4) ? ch * 384 : 1536 + (ch - 4) * 256;
    const int K  = (ch < 4) ? 384 : 256;

    size_t xo = (size_t)bq * 524288;
    const __half* A = g_Xt + xo + (size_t)mt * 128 * 2048 + k0;
    const __half* B = g_Xt + xo + (size_t)nt * 128 * 2048 + k0;
    float* Cf = g_Gpart + (size_t)((ch * 8 + bq) * 3 + t) * 16384;
    gemm128(A, 2048, B, 2048, K, Cf, 128);
}

// ============================================================================
extern "C" void kernel_launch(void* const* d_in, const int* in_sizes, int n_in,
                              void* d_out, int out_size)
{
    const float* hidden    = (const float*)d_in[0];  // [2,2048,1024]
    const float* queries   = (const float*)d_in[1];  // [4,256,1024]
    const float* combiners = (const float*)d_in[2];  // [4,1024,256]
    float* out = (float*)d_out;
    (void)in_sizes; (void)n_in; (void)out_size;

    cudaFuncSetAttribute(k_s1,  cudaFuncAttributeMaxDynamicSharedMemorySize, SMEM_G);
    cudaFuncSetAttribute(k_s23, cudaFuncAttributeMaxDynamicSharedMemorySize, SMEM_23);
    cudaFuncSetAttribute(k_s4,  cudaFuncAttributeMaxDynamicSharedMemorySize, SMEM_S4);

    k_conv_x<<<4096, 256>>>(hidden);

    cudaLaunchAttribute at;
    at.id = cudaLaunchAttributeProgrammaticStreamSerialization;
    at.val.programmaticStreamSerializationAllowed = 1;

    {   // s1: PDL after conv_x
        cudaLaunchConfig_t cfg = {};
        cfg.gridDim = dim3(3, 6, 8); cfg.blockDim = dim3(256, 1, 1);
        cfg.dynamicSmemBytes = SMEM_G; cfg.stream = 0;
        cfg.attrs = &at; cfg.numAttrs = 1;
        cudaLaunchKernelEx(&cfg, k_s1);
    }
    {   // conv_wc: PDL after s1 (s1 signals at start) => runs DURING s1
        cudaLaunchConfig_t cfg = {};
        cfg.gridDim = dim3(2048, 1, 1); cfg.blockDim = dim3(256, 1, 1);
        cfg.dynamicSmemBytes = 0; cfg.stream = 0;
        cfg.attrs = &at; cfg.numAttrs = 1;
        cudaLaunchKernelEx(&cfg, k_conv_wc, queries, combiners);
    }
    {   // reduceG: NO PDL attr => waits completion of s1 AND conv_wc
        cudaLaunchConfig_t cfg = {};
        cfg.gridDim = dim3(16, 3, 8); cfg.blockDim = dim3(256, 1, 1);
        cfg.dynamicSmemBytes = 0; cfg.stream = 0;
        cudaLaunchKernelEx(&cfg, k_reduceG);
    }
    {   // s23: PDL after reduceG (prefetches W pre-wait)
        cudaLaunchConfig_t cfg = {};
        cfg.gridDim = dim3(4, 1, 32); cfg.blockDim = dim3(256, 1, 1);
        cfg.dynamicSmemBytes = SMEM_23; cfg.stream = 0;
        cfg.attrs = &at; cfg.numAttrs = 1;
        cudaLaunchKernelEx(&cfg, k_s23);
    }
    {   // reduceP: PDL after s23
        cudaLaunchConfig_t cfg = {};
        cfg.gridDim = dim3(8, 8, 8); cfg.blockDim = dim3(256, 1, 1);
        cfg.dynamicSmemBytes = 0; cfg.stream = 0;
        cfg.attrs = &at; cfg.numAttrs = 1;
        cudaLaunchKernelEx(&cfg, k_reduceP);
    }
    {   // s4: PDL after reduceP (prefetches both A chunks pre-wait)
        cudaLaunchConfig_t cfg = {};
        cfg.gridDim = dim3(16, 1, 8); cfg.blockDim = dim3(256, 1, 1);
        cfg.dynamicSmemBytes = SMEM_S4; cfg.stream = 0;
        cfg.attrs = &at; cfg.numAttrs = 1;
        cudaLaunchKernelEx(&cfg, k_s4, out);
    }
}